// round 6
// baseline (speedup 1.0000x reference)
#include <cuda_runtime.h>
#include <cuda_bf16.h>
#include <mma.h>
#include <math.h>

using namespace nvcuda;

// ---------------------------------------------------------------------------
// Problem constants
// ---------------------------------------------------------------------------
#define Bv   8
#define Tv   1024
#define Fv   64
#define DMv  256
#define Lv   4
#define DIv  512          // 2*DM
#define Nv   16
#define DCv  4
#define DTRv 16           // DM/16
#define BT   (Bv*Tv)      // 8192

// ---------------------------------------------------------------------------
// Scratch (device globals; no runtime allocation allowed)
// ---------------------------------------------------------------------------
__device__ float g_h  [BT * DMv];        // hidden (fp32, for final LN)
__device__ float g_xz [BT * (2*DIv)];    // in_proj output (xc_raw | z)
__device__ float g_xc [BT * DIv];        // conv+silu output (u)
__device__ float g_dt [BT * DIv];        // softplus(dt)
__device__ float g_BC [BT * (2*Nv)];     // B | C

// bf16 hi/lo activation buffers (GEMM A operands)
__device__ __nv_bfloat16 g_xhi[BT * Fv],  g_xlo[BT * Fv];
__device__ __nv_bfloat16 g_hhi[BT * DMv], g_hlo[BT * DMv];
__device__ __nv_bfloat16 g_yhi[BT * DIv], g_ylo[BT * DIv];

// split-bf16 weight buffers: proj_w[16384] | ipw[1048576] | opw[524288]
__device__ __nv_bfloat16 g_whi[1589248];
__device__ __nv_bfloat16 g_wlo[1589248];

// ---------------------------------------------------------------------------
// Vectorized split: fp32 -> (hi, lo) bf16, 4 elements per thread.
// n must be a multiple of 4 (all our sizes are multiples of 1024).
// ---------------------------------------------------------------------------
__global__ void __launch_bounds__(256)
split4_kernel(const float* __restrict__ w, __nv_bfloat16* __restrict__ hi,
              __nv_bfloat16* __restrict__ lo, int n4)
{
    int i = blockIdx.x * 256 + threadIdx.x;
    if (i < n4) {
        const float4 v = *(const float4*)(w + i*4);
        __nv_bfloat16 h0 = __float2bfloat16(v.x);
        __nv_bfloat16 h1 = __float2bfloat16(v.y);
        __nv_bfloat16 h2 = __float2bfloat16(v.z);
        __nv_bfloat16 h3 = __float2bfloat16(v.w);
        __nv_bfloat162 a; a.x = h0; a.y = h1;
        __nv_bfloat162 b; b.x = h2; b.y = h3;
        *(__nv_bfloat162*)(hi + i*4)     = a;
        *(__nv_bfloat162*)(hi + i*4 + 2) = b;
        __nv_bfloat162 c; c.x = __float2bfloat16(v.x - __bfloat162float(h0));
                          c.y = __float2bfloat16(v.y - __bfloat162float(h1));
        __nv_bfloat162 d; d.x = __float2bfloat16(v.z - __bfloat162float(h2));
                          d.y = __float2bfloat16(v.w - __bfloat162float(h3));
        *(__nv_bfloat162*)(lo + i*4)     = c;
        *(__nv_bfloat162*)(lo + i*4 + 2) = d;
    }
}

// Same but adds a 256-periodic bias first (input-projection epilogue).
__global__ void __launch_bounds__(256)
bias_split4_kernel(const float* __restrict__ w, const float* __restrict__ bias,
                   __nv_bfloat16* __restrict__ hi, __nv_bfloat16* __restrict__ lo,
                   int n4)
{
    int i = blockIdx.x * 256 + threadIdx.x;
    if (i < n4) {
        float4 v = *(const float4*)(w + i*4);
        const float4 bb = *(const float4*)(bias + ((i*4) & 255));
        v.x += bb.x; v.y += bb.y; v.z += bb.z; v.w += bb.w;
        __nv_bfloat16 h0 = __float2bfloat16(v.x);
        __nv_bfloat16 h1 = __float2bfloat16(v.y);
        __nv_bfloat16 h2 = __float2bfloat16(v.z);
        __nv_bfloat16 h3 = __float2bfloat16(v.w);
        __nv_bfloat162 a; a.x = h0; a.y = h1;
        __nv_bfloat162 b; b.x = h2; b.y = h3;
        *(__nv_bfloat162*)(hi + i*4)     = a;
        *(__nv_bfloat162*)(hi + i*4 + 2) = b;
        __nv_bfloat162 c; c.x = __float2bfloat16(v.x - __bfloat162float(h0));
                          c.y = __float2bfloat16(v.y - __bfloat162float(h1));
        __nv_bfloat162 d; d.x = __float2bfloat16(v.z - __bfloat162float(h2));
                          d.y = __float2bfloat16(v.w - __bfloat162float(h3));
        *(__nv_bfloat162*)(lo + i*4)     = c;
        *(__nv_bfloat162*)(lo + i*4 + 2) = d;
    }
}

// ---------------------------------------------------------------------------
// Tensor-core GEMM, fp32 emulation via 2-term bf16 split, register
// double-buffered.  C[M,N] = A[M,K] @ W[N,K]^T.  BM=BN=128, BK=32,
// 256 threads, 8 warps as 2(m) x 4(n), warp tile 64x32.
// Requires M%128==0, N%128==0, K%32==0.
// ---------------------------------------------------------------------------
#define SPAD 40

__global__ void __launch_bounds__(256)
wgemm_nt_kernel(const __nv_bfloat16* __restrict__ Ahi,
                const __nv_bfloat16* __restrict__ Alo,
                const __nv_bfloat16* __restrict__ Whi,
                const __nv_bfloat16* __restrict__ Wlo,
                float* __restrict__ C,
                int M, int N, int K)
{
    __shared__ __align__(16) __nv_bfloat16 Ah[128*SPAD];
    __shared__ __align__(16) __nv_bfloat16 Al[128*SPAD];
    __shared__ __align__(16) __nv_bfloat16 Bh[128*SPAD];
    __shared__ __align__(16) __nv_bfloat16 Bl[128*SPAD];

    const int tid = threadIdx.x;
    const int bm  = blockIdx.y, bn = blockIdx.x;
    const int wid = tid >> 5;
    const int wm  = wid >> 2;        // 0..1  -> 64 rows each
    const int wn  = wid & 3;         // 0..3  -> 32 cols each

    // staging coordinates: each thread owns rows (r0, r0+64) at kc
    const int r0 = tid >> 2;              // 0..63
    const int kc = (tid & 3) << 3;        // 0,8,16,24

    const __nv_bfloat16* pa0 = Ahi + (size_t)(bm*128 + r0) * K + kc;
    const __nv_bfloat16* pa1 = pa0 + (size_t)64 * K;
    const __nv_bfloat16* la0 = Alo + (size_t)(bm*128 + r0) * K + kc;
    const __nv_bfloat16* la1 = la0 + (size_t)64 * K;
    const __nv_bfloat16* pb0 = Whi + (size_t)(bn*128 + r0) * K + kc;
    const __nv_bfloat16* pb1 = pb0 + (size_t)64 * K;
    const __nv_bfloat16* lb0 = Wlo + (size_t)(bn*128 + r0) * K + kc;
    const __nv_bfloat16* lb1 = lb0 + (size_t)64 * K;

    wmma::fragment<wmma::accumulator, 16, 16, 16, float> acc[4][2];
#pragma unroll
    for (int mi = 0; mi < 4; ++mi)
#pragma unroll
        for (int ni = 0; ni < 2; ++ni)
            wmma::fill_fragment(acc[mi][ni], 0.0f);

    // ---- prologue: load + store tile 0 ------------------------------------
    float4 rah0 = *(const float4*)(pa0);
    float4 rah1 = *(const float4*)(pa1);
    float4 ral0 = *(const float4*)(la0);
    float4 ral1 = *(const float4*)(la1);
    float4 rbh0 = *(const float4*)(pb0);
    float4 rbh1 = *(const float4*)(pb1);
    float4 rbl0 = *(const float4*)(lb0);
    float4 rbl1 = *(const float4*)(lb1);

    *(float4*)(Ah + r0*SPAD + kc)        = rah0;
    *(float4*)(Ah + (r0+64)*SPAD + kc)   = rah1;
    *(float4*)(Al + r0*SPAD + kc)        = ral0;
    *(float4*)(Al + (r0+64)*SPAD + kc)   = ral1;
    *(float4*)(Bh + r0*SPAD + kc)        = rbh0;
    *(float4*)(Bh + (r0+64)*SPAD + kc)   = rbh1;
    *(float4*)(Bl + r0*SPAD + kc)        = rbl0;
    *(float4*)(Bl + (r0+64)*SPAD + kc)   = rbl1;
    __syncthreads();

    for (int k0 = 32; k0 <= K; k0 += 32) {
        // ---- prefetch next tile into registers (overlaps with MMAs) -------
        if (k0 < K) {
            rah0 = *(const float4*)(pa0 + k0);
            rah1 = *(const float4*)(pa1 + k0);
            ral0 = *(const float4*)(la0 + k0);
            ral1 = *(const float4*)(la1 + k0);
            rbh0 = *(const float4*)(pb0 + k0);
            rbh1 = *(const float4*)(pb1 + k0);
            rbl0 = *(const float4*)(lb0 + k0);
            rbl1 = *(const float4*)(lb1 + k0);
        }

        // ---- compute current tile from smem --------------------------------
#pragma unroll
        for (int ks = 0; ks < 32; ks += 16) {
            wmma::fragment<wmma::matrix_a, 16, 16, 16, __nv_bfloat16, wmma::row_major> aH[4], aL[4];
#pragma unroll
            for (int mi = 0; mi < 4; ++mi) {
                const int rr = wm*64 + mi*16;
                wmma::load_matrix_sync(aH[mi], Ah + rr*SPAD + ks, SPAD);
                wmma::load_matrix_sync(aL[mi], Al + rr*SPAD + ks, SPAD);
            }
            wmma::fragment<wmma::matrix_b, 16, 16, 16, __nv_bfloat16, wmma::col_major> bH[2], bL[2];
#pragma unroll
            for (int ni = 0; ni < 2; ++ni) {
                const int rr = wn*32 + ni*16;
                wmma::load_matrix_sync(bH[ni], Bh + rr*SPAD + ks, SPAD);
                wmma::load_matrix_sync(bL[ni], Bl + rr*SPAD + ks, SPAD);
            }
#pragma unroll
            for (int mi = 0; mi < 4; ++mi)
#pragma unroll
                for (int ni = 0; ni < 2; ++ni) {
                    wmma::mma_sync(acc[mi][ni], aH[mi], bH[ni], acc[mi][ni]);
                    wmma::mma_sync(acc[mi][ni], aH[mi], bL[ni], acc[mi][ni]);
                    wmma::mma_sync(acc[mi][ni], aL[mi], bH[ni], acc[mi][ni]);
                }
        }

        // ---- rotate buffers -------------------------------------------------
        if (k0 < K) {
            __syncthreads();
            *(float4*)(Ah + r0*SPAD + kc)      = rah0;
            *(float4*)(Ah + (r0+64)*SPAD + kc) = rah1;
            *(float4*)(Al + r0*SPAD + kc)      = ral0;
            *(float4*)(Al + (r0+64)*SPAD + kc) = ral1;
            *(float4*)(Bh + r0*SPAD + kc)      = rbh0;
            *(float4*)(Bh + (r0+64)*SPAD + kc) = rbh1;
            *(float4*)(Bl + r0*SPAD + kc)      = rbl0;
            *(float4*)(Bl + (r0+64)*SPAD + kc) = rbl1;
            __syncthreads();
        }
    }

#pragma unroll
    for (int mi = 0; mi < 4; ++mi)
#pragma unroll
        for (int ni = 0; ni < 2; ++ni) {
            const int rr = bm*128 + wm*64 + mi*16;
            const int cc = bn*128 + wn*32 + ni*16;
            wmma::store_matrix_sync(C + (size_t)rr * N + cc, acc[mi][ni], N,
                                    wmma::mem_row_major);
        }
}

// ---------------------------------------------------------------------------
// Fused middle kernel (per layer): conv(4)+bias+SiLU -> x_proj -> dt_proj
// + softplus.  16 timesteps per block, 512 blocks, 256 threads.
// ---------------------------------------------------------------------------
__global__ void __launch_bounds__(256)
fused_mid_kernel(const float* __restrict__ conv_w,
                 const float* __restrict__ conv_b,
                 const float* __restrict__ xpw,
                 const float* __restrict__ dtw,
                 const float* __restrict__ dtb)
{
    __shared__ float xc_s  [16][DIv];
    __shared__ float wc_s  [48][66];
    __shared__ float xdbl_s[16][48];

    const int blk = blockIdx.x;
    const int b   = blk >> 6;
    const int t0  = (blk & 63) << 4;
    const int tid = threadIdx.x;

#pragma unroll
    for (int dd = 0; dd < 2; ++dd) {
        const int d = tid + dd * 256;
        const float* xin = g_xz + (size_t)(b * Tv) * (2*DIv) + d;
        const float4 cw4 = *(const float4*)(conv_w + d*4);
        const float  cb  = conv_b[d];
        float x0 = (t0 - 3 >= 0) ? xin[(size_t)(t0-3) * (2*DIv)] : 0.f;
        float x1 = (t0 - 2 >= 0) ? xin[(size_t)(t0-2) * (2*DIv)] : 0.f;
        float x2 = (t0 - 1 >= 0) ? xin[(size_t)(t0-1) * (2*DIv)] : 0.f;
#pragma unroll
        for (int tt = 0; tt < 16; ++tt) {
            const float x3 = xin[(size_t)(t0+tt) * (2*DIv)];
            float s = cw4.x*x0 + cw4.y*x1 + cw4.z*x2 + cw4.w*x3 + cb;
            float sl = s / (1.f + __expf(-s));
            xc_s[tt][d] = sl;
            g_xc[((size_t)(b*Tv + t0 + tt)) * DIv + d] = sl;
            x0 = x1; x1 = x2; x2 = x3;
        }
    }
    __syncthreads();

    const int tt  = tid >> 4;
    const int oth = tid & 15;
    float acc0 = 0.f, acc1 = 0.f, acc2 = 0.f;

    for (int kc = 0; kc < DIv; kc += 64) {
#pragma unroll
        for (int j = 0; j < 3; ++j) {
            const int l4 = tid * 3 + j;
            const int o  = l4 >> 4;
            const int k  = (l4 & 15) << 2;
            const float4 v = *(const float4*)(xpw + o*DIv + kc + k);
            wc_s[o][k+0] = v.x; wc_s[o][k+1] = v.y;
            wc_s[o][k+2] = v.z; wc_s[o][k+3] = v.w;
        }
        __syncthreads();
#pragma unroll 8
        for (int k = 0; k < 64; ++k) {
            const float a = xc_s[tt][kc + k];
            acc0 += a * wc_s[oth      ][k];
            acc1 += a * wc_s[oth + 16][k];
            acc2 += a * wc_s[oth + 32][k];
        }
        __syncthreads();
    }
    xdbl_s[tt][oth     ] = acc0;
    xdbl_s[tt][oth + 16] = acc1;
    xdbl_s[tt][oth + 32] = acc2;
    __syncthreads();

    {
        int idx = tid;
#pragma unroll
        for (int r = 0; r < 2; ++r, idx += 256) {
            const int tti = idx >> 5, c = idx & 31;
            g_BC[((size_t)(b*Tv + t0 + tti)) * (2*Nv) + c] = xdbl_s[tti][16 + c];
        }
    }

#pragma unroll
    for (int dd = 0; dd < 2; ++dd) {
        const int d = tid + dd * 256;
        float w[16];
        *(float4*)&w[0]  = *(const float4*)(dtw + d*16 + 0);
        *(float4*)&w[4]  = *(const float4*)(dtw + d*16 + 4);
        *(float4*)&w[8]  = *(const float4*)(dtw + d*16 + 8);
        *(float4*)&w[12] = *(const float4*)(dtw + d*16 + 12);
        const float bia = dtb[d];
#pragma unroll
        for (int tt2 = 0; tt2 < 16; ++tt2) {
            float s = bia;
#pragma unroll
            for (int r = 0; r < 16; ++r) s += xdbl_s[tt2][r] * w[r];
            float sp = fmaxf(s, 0.f) + log1pf(__expf(-fabsf(s)));
            g_dt[((size_t)(b*Tv + t0 + tt2)) * DIv + d] = sp;
        }
    }
}

// ---------------------------------------------------------------------------
// Selective scan: smem-chunked.  grid = (32, 8), 256 threads.
// ---------------------------------------------------------------------------
__global__ void __launch_bounds__(256)
scan2_kernel(const float* __restrict__ A_log, const float* __restrict__ Dp)
{
    __shared__ float s_dt[64][16];
    __shared__ float s_u [64][16];
    __shared__ float s_z [64][16];
    __shared__ float s_bc[64][32];

    const int d0   = blockIdx.x * 16;
    const int b    = blockIdx.y;
    const int tid  = threadIdx.x;
    const int warp = tid >> 5;
    const int lane = tid & 31;
    const int half = lane >> 4;
    const int n    = lane & 15;
    const int dloc = warp * 2 + half;
    const int d    = d0 + dloc;

    const float a     = -__expf(A_log[d * Nv + n]);
    const float dcoef = Dp[d];
    float h = 0.f;

    for (int tc = 0; tc < Tv; tc += 64) {
        const int base = b * Tv + tc;
#pragma unroll
        for (int i = 0; i < 4; ++i) {
            const int idx = tid + i * 256;
            const int tt  = idx >> 4;
            const int dd  = idx & 15;
            s_dt[tt][dd] = g_dt[(size_t)(base + tt) * DIv + d0 + dd];
            s_u [tt][dd] = g_xc[(size_t)(base + tt) * DIv + d0 + dd];
            s_z [tt][dd] = g_xz[(size_t)(base + tt) * (2*DIv) + DIv + d0 + dd];
        }
#pragma unroll
        for (int i = 0; i < 8; ++i) {
            const int idx = tid + i * 256;
            const int tt  = idx >> 5;
            const int c   = idx & 31;
            s_bc[tt][c] = g_BC[(size_t)(base + tt) * (2*Nv) + c];
        }
        __syncthreads();

#pragma unroll 4
        for (int tt = 0; tt < 64; ++tt) {
            const float dtv = s_dt[tt][dloc];
            const float uv  = s_u [tt][dloc];
            const float bv  = s_bc[tt][n];
            const float cv  = s_bc[tt][Nv + n];

            const float dA = __expf(dtv * a);
            h = dA * h + (dtv * uv) * bv;

            float part = h * cv;
            part += __shfl_xor_sync(0xffffffffu, part, 1);
            part += __shfl_xor_sync(0xffffffffu, part, 2);
            part += __shfl_xor_sync(0xffffffffu, part, 4);
            part += __shfl_xor_sync(0xffffffffu, part, 8);

            if (n == 0) {
                const float zv = s_z[tt][dloc];
                float y = part + dcoef * uv;
                y *= zv / (1.f + __expf(-zv));
                __nv_bfloat16 yh = __float2bfloat16(y);
                const size_t o = (size_t)(base + tt) * DIv + d;
                g_yhi[o] = yh;
                g_ylo[o] = __float2bfloat16(y - __bfloat162float(yh));
            }
        }
        __syncthreads();
    }
}

// ---------------------------------------------------------------------------
// Final: LayerNorm(last token) + head.
// ---------------------------------------------------------------------------
__global__ void __launch_bounds__(256)
final_kernel(const float* __restrict__ ln_g, const float* __restrict__ ln_b,
             const float* __restrict__ head_w, const float* __restrict__ head_b,
             float* __restrict__ out)
{
    __shared__ float red[256];
    const int b = blockIdx.x, tid = threadIdx.x;
    const float v = g_h[((size_t)(b * Tv + (Tv - 1))) * DMv + tid];

    red[tid] = v; __syncthreads();
    for (int s = 128; s > 0; s >>= 1) { if (tid < s) red[tid] += red[tid + s]; __syncthreads(); }
    const float mu = red[0] * (1.f / DMv);
    __syncthreads();

    const float dv = v - mu;
    red[tid] = dv * dv; __syncthreads();
    for (int s = 128; s > 0; s >>= 1) { if (tid < s) red[tid] += red[tid + s]; __syncthreads(); }
    const float var = red[0] * (1.f / DMv);
    __syncthreads();

    const float hn = dv * rsqrtf(var + 1e-5f) * ln_g[tid] + ln_b[tid];
    red[tid] = hn * head_w[tid]; __syncthreads();
    for (int s = 128; s > 0; s >>= 1) { if (tid < s) red[tid] += red[tid + s]; __syncthreads(); }
    if (tid == 0) out[b] = red[0] + head_b[0];
}

// ---------------------------------------------------------------------------
// Host launcher
// ---------------------------------------------------------------------------
extern "C" void kernel_launch(void* const* d_in, const int* in_sizes, int n_in,
                              void* d_out, int out_size)
{
    const float* x      = (const float*)d_in[0];
    const float* proj_w = (const float*)d_in[1];
    const float* proj_b = (const float*)d_in[2];
    const float* ipw    = (const float*)d_in[3];
    const float* cw     = (const float*)d_in[4];
    const float* cb     = (const float*)d_in[5];
    const float* xpw    = (const float*)d_in[6];
    const float* dtw    = (const float*)d_in[7];
    const float* dtb    = (const float*)d_in[8];
    const float* A_log  = (const float*)d_in[9];
    const float* Dp     = (const float*)d_in[10];
    const float* opw    = (const float*)d_in[11];
    const float* ln_g   = (const float*)d_in[12];
    const float* ln_b   = (const float*)d_in[13];
    const float* head_w = (const float*)d_in[14];
    const float* head_b = (const float*)d_in[15];
    float* out = (float*)d_out;

    float *hbuf, *xzbuf;
    __nv_bfloat16 *whi, *wlo, *xhi, *xlo, *hhi, *hlo, *yhi, *ylo;
    cudaGetSymbolAddress((void**)&hbuf,  g_h);
    cudaGetSymbolAddress((void**)&xzbuf, g_xz);
    cudaGetSymbolAddress((void**)&whi,   g_whi);
    cudaGetSymbolAddress((void**)&wlo,   g_wlo);
    cudaGetSymbolAddress((void**)&xhi,   g_xhi);
    cudaGetSymbolAddress((void**)&xlo,   g_xlo);
    cudaGetSymbolAddress((void**)&hhi,   g_hhi);
    cudaGetSymbolAddress((void**)&hlo,   g_hlo);
    cudaGetSymbolAddress((void**)&yhi,   g_yhi);
    cudaGetSymbolAddress((void**)&ylo,   g_ylo);

    __nv_bfloat16* whi_proj = whi;
    __nv_bfloat16* wlo_proj = wlo;
    __nv_bfloat16* whi_ipw  = whi + 16384;
    __nv_bfloat16* wlo_ipw  = wlo + 16384;
    __nv_bfloat16* whi_opw  = whi + 1064960;
    __nv_bfloat16* wlo_opw  = wlo + 1064960;

    // weights + input -> bf16 hi/lo (vectorized; counts are n/4)
    split4_kernel<<<16, 256>>>(proj_w, whi_proj, wlo_proj, 4096);
    split4_kernel<<<1024, 256>>>(ipw, whi_ipw, wlo_ipw, 262144);
    split4_kernel<<<512, 256>>>(opw, whi_opw, wlo_opw, 131072);
    split4_kernel<<<512, 256>>>(x, xhi, xlo, 131072);

    dim3 grid_in(2, 64);      // N=256/128,  M=8192/128
    dim3 grid_ip(8, 64);      // N=1024/128
    dim3 grid_op(2, 64);      // N=256/128
    dim3 grid_sc(32, 8);      // channel groups x batches

    // input projection: h = x @ proj_w^T (+bias fused into split) [8192,256]
    wgemm_nt_kernel<<<grid_in, 256>>>(xhi, xlo, whi_proj, wlo_proj, hbuf,
                                      BT, DMv, Fv);
    bias_split4_kernel<<<2048, 256>>>(hbuf, proj_b, hhi, hlo, 524288);

    for (int l = 0; l < Lv; ++l) {
        const size_t ipoff = (size_t)l * 262144;   // (2*DIv)*DMv
        const size_t opoff = (size_t)l * 131072;   // DMv*DIv

        // in_proj: xz = h @ ipw^T   [8192,1024], K=256
        wgemm_nt_kernel<<<grid_ip, 256>>>(hhi, hlo,
                                          whi_ipw + ipoff, wlo_ipw + ipoff,
                                          xzbuf, BT, 2*DIv, DMv);

        fused_mid_kernel<<<512, 256>>>(
            cw  + (size_t)l * DIv * DCv,
            cb  + (size_t)l * DIv,
            xpw + (size_t)l * (DTRv + 2*Nv) * DIv,
            dtw + (size_t)l * DIv * DTRv,
            dtb + (size_t)l * DIv);

        scan2_kernel<<<grid_sc, 256>>>(A_log + (size_t)l * DIv * Nv,
                                       Dp    + (size_t)l * DIv);

        // out_proj: h = y @ opw^T   [8192,256], K=512
        wgemm_nt_kernel<<<grid_op, 256>>>(yhi, ylo,
                                          whi_opw + opoff, wlo_opw + opoff,
                                          hbuf, BT, DMv, DIv);

        if (l < Lv - 1)
            split4_kernel<<<2048, 256>>>(hbuf, hhi, hlo, 524288);
    }

    final_kernel<<<Bv, 256>>>(ln_g, ln_b, head_w, head_b, out);
}

// round 7
// speedup vs baseline: 1.0729x; 1.0729x over previous
#include <cuda_runtime.h>
#include <cuda_bf16.h>
#include <mma.h>
#include <math.h>

using namespace nvcuda;

// ---------------------------------------------------------------------------
// Problem constants
// ---------------------------------------------------------------------------
#define Bv   8
#define Tv   1024
#define Fv   64
#define DMv  256
#define Lv   4
#define DIv  512          // 2*DM
#define Nv   16
#define DCv  4
#define DTRv 16           // DM/16
#define BT   (Bv*Tv)      // 8192

// ---------------------------------------------------------------------------
// Scratch (device globals; no runtime allocation allowed)
// ---------------------------------------------------------------------------
__device__ float g_h  [BT * DMv];        // hidden (fp32)
__device__ float g_xz [BT * (2*DIv)];    // in_proj output (xc_raw | z)
__device__ float g_xc [BT * DIv];        // conv+silu output (u)
__device__ float g_dt [BT * DIv];        // softplus(dt)
__device__ float g_BC [BT * (2*Nv)];     // B | C
__device__ float g_y  [BT * DIv];        // gated scan output

// split-bf16 weight buffers: proj_w[16384] | ipw[1048576] | opw[524288]
__device__ __nv_bfloat16 g_whi[1589248];
__device__ __nv_bfloat16 g_wlo[1589248];

// ---------------------------------------------------------------------------
// Weight splits (vectorized, 4 elems/thread).
// ---------------------------------------------------------------------------
__global__ void __launch_bounds__(256)
split4_kernel(const float* __restrict__ w, __nv_bfloat16* __restrict__ hi,
              __nv_bfloat16* __restrict__ lo, int n4)
{
    int i = blockIdx.x * 256 + threadIdx.x;
    if (i < n4) {
        const float4 v = *(const float4*)(w + i*4);
        __nv_bfloat16 h0 = __float2bfloat16(v.x);
        __nv_bfloat16 h1 = __float2bfloat16(v.y);
        __nv_bfloat16 h2 = __float2bfloat16(v.z);
        __nv_bfloat16 h3 = __float2bfloat16(v.w);
        __nv_bfloat162 a; a.x = h0; a.y = h1;
        __nv_bfloat162 b; b.x = h2; b.y = h3;
        *(__nv_bfloat162*)(hi + i*4)     = a;
        *(__nv_bfloat162*)(hi + i*4 + 2) = b;
        __nv_bfloat162 c; c.x = __float2bfloat16(v.x - __bfloat162float(h0));
                          c.y = __float2bfloat16(v.y - __bfloat162float(h1));
        __nv_bfloat162 d; d.x = __float2bfloat16(v.z - __bfloat162float(h2));
                          d.y = __float2bfloat16(v.w - __bfloat162float(h3));
        *(__nv_bfloat162*)(lo + i*4)     = c;
        *(__nv_bfloat162*)(lo + i*4 + 2) = d;
    }
}

// proj_w (4096 float4s) and opw (131072 float4s) in one launch.
__global__ void __launch_bounds__(256)
split_misc_kernel(const float* __restrict__ proj_w, const float* __restrict__ opw,
                  __nv_bfloat16* __restrict__ hi_proj, __nv_bfloat16* __restrict__ lo_proj,
                  __nv_bfloat16* __restrict__ hi_opw,  __nv_bfloat16* __restrict__ lo_opw)
{
    int i = blockIdx.x * 256 + threadIdx.x;     // 0 .. 135167
    const float* src;
    __nv_bfloat16 *hi, *lo;
    int j;
    if (i < 4096)      { src = proj_w; hi = hi_proj; lo = lo_proj; j = i; }
    else if (i < 135168) { src = opw;  hi = hi_opw;  lo = lo_opw;  j = i - 4096; }
    else return;
    const float4 v = *(const float4*)(src + j*4);
    __nv_bfloat16 h0 = __float2bfloat16(v.x);
    __nv_bfloat16 h1 = __float2bfloat16(v.y);
    __nv_bfloat16 h2 = __float2bfloat16(v.z);
    __nv_bfloat16 h3 = __float2bfloat16(v.w);
    __nv_bfloat162 a; a.x = h0; a.y = h1;
    __nv_bfloat162 b; b.x = h2; b.y = h3;
    *(__nv_bfloat162*)(hi + j*4)     = a;
    *(__nv_bfloat162*)(hi + j*4 + 2) = b;
    __nv_bfloat162 c; c.x = __float2bfloat16(v.x - __bfloat162float(h0));
                      c.y = __float2bfloat16(v.y - __bfloat162float(h1));
    __nv_bfloat162 d; d.x = __float2bfloat16(v.z - __bfloat162float(h2));
                      d.y = __float2bfloat16(v.w - __bfloat162float(h3));
    *(__nv_bfloat162*)(lo + j*4)     = c;
    *(__nv_bfloat162*)(lo + j*4 + 2) = d;
}

// ---------------------------------------------------------------------------
// Tensor-core GEMM, fp32 emulation via 2-term bf16 split.
// C[M,N] = (A + Abias_row) [M,K] @ W[N,K]^T.  A fp32, split hi/lo on the fly
// during smem staging.  Abias (optional) is added along K columns.
// W pre-split bf16 hi/lo.  BM=BN=128, BK=32, 256 threads, 8 warps 2(m)x4(n).
// ---------------------------------------------------------------------------
#define SPAD 40

__global__ void __launch_bounds__(256)
wgemm_nt_kernel(const float* __restrict__ A, const float* __restrict__ Abias,
                const __nv_bfloat16* __restrict__ Whi,
                const __nv_bfloat16* __restrict__ Wlo,
                float* __restrict__ C,
                int M, int N, int K)
{
    __shared__ __align__(16) __nv_bfloat16 Ah[128*SPAD];
    __shared__ __align__(16) __nv_bfloat16 Al[128*SPAD];
    __shared__ __align__(16) __nv_bfloat16 Bh[128*SPAD];
    __shared__ __align__(16) __nv_bfloat16 Bl[128*SPAD];

    const int tid = threadIdx.x;
    const int bm  = blockIdx.y, bn = blockIdx.x;
    const int wid = tid >> 5;
    const int wm  = wid >> 2;        // 0..1  -> 64 rows each
    const int wn  = wid & 3;         // 0..3  -> 32 cols each

    wmma::fragment<wmma::accumulator, 16, 16, 16, float> acc[4][2];
#pragma unroll
    for (int mi = 0; mi < 4; ++mi)
#pragma unroll
        for (int ni = 0; ni < 2; ++ni)
            wmma::fill_fragment(acc[mi][ni], 0.0f);

    for (int k0 = 0; k0 < K; k0 += 32) {
        // ---- stage A (fp32 -> hi/lo, + optional K-column bias) -------------
#pragma unroll
        for (int i = 0; i < 4; ++i) {
            const int idx = tid + i * 256;       // 0..1023 float4s
            const int row = idx >> 3;            // 8 float4 per 32-wide row
            const int kc  = (idx & 7) << 2;
            float4 v = *(const float4*)(A + (size_t)(bm*128 + row) * K + k0 + kc);
            if (Abias) {
                const float4 bb = *(const float4*)(Abias + k0 + kc);
                v.x += bb.x; v.y += bb.y; v.z += bb.z; v.w += bb.w;
            }
            __nv_bfloat16 h0 = __float2bfloat16(v.x);
            __nv_bfloat16 h1 = __float2bfloat16(v.y);
            __nv_bfloat16 h2 = __float2bfloat16(v.z);
            __nv_bfloat16 h3 = __float2bfloat16(v.w);
            __nv_bfloat162 ph0; ph0.x = h0; ph0.y = h1;
            __nv_bfloat162 ph1; ph1.x = h2; ph1.y = h3;
            *(__nv_bfloat162*)(Ah + row*SPAD + kc)     = ph0;
            *(__nv_bfloat162*)(Ah + row*SPAD + kc + 2) = ph1;
            __nv_bfloat162 pl0; pl0.x = __float2bfloat16(v.x - __bfloat162float(h0));
                                pl0.y = __float2bfloat16(v.y - __bfloat162float(h1));
            __nv_bfloat162 pl1; pl1.x = __float2bfloat16(v.z - __bfloat162float(h2));
                                pl1.y = __float2bfloat16(v.w - __bfloat162float(h3));
            *(__nv_bfloat162*)(Al + row*SPAD + kc)     = pl0;
            *(__nv_bfloat162*)(Al + row*SPAD + kc + 2) = pl1;
        }
        // ---- stage W tiles (bf16 direct) -----------------------------------
#pragma unroll
        for (int i = 0; i < 2; ++i) {
            const int idx = tid + i * 256;       // 0..511 float4s (8 halves)
            const int row = idx >> 2;
            const int kc  = (idx & 3) << 3;
            const size_t g = (size_t)(bn*128 + row) * K + k0 + kc;
            *(float4*)(Bh + row*SPAD + kc) = *(const float4*)(Whi + g);
            *(float4*)(Bl + row*SPAD + kc) = *(const float4*)(Wlo + g);
        }
        __syncthreads();

#pragma unroll
        for (int ks = 0; ks < 32; ks += 16) {
            wmma::fragment<wmma::matrix_a, 16, 16, 16, __nv_bfloat16, wmma::row_major> aH[4], aL[4];
#pragma unroll
            for (int mi = 0; mi < 4; ++mi) {
                const int rr = wm*64 + mi*16;
                wmma::load_matrix_sync(aH[mi], Ah + rr*SPAD + ks, SPAD);
                wmma::load_matrix_sync(aL[mi], Al + rr*SPAD + ks, SPAD);
            }
            wmma::fragment<wmma::matrix_b, 16, 16, 16, __nv_bfloat16, wmma::col_major> bH[2], bL[2];
#pragma unroll
            for (int ni = 0; ni < 2; ++ni) {
                const int rr = wn*32 + ni*16;
                wmma::load_matrix_sync(bH[ni], Bh + rr*SPAD + ks, SPAD);
                wmma::load_matrix_sync(bL[ni], Bl + rr*SPAD + ks, SPAD);
            }
#pragma unroll
            for (int mi = 0; mi < 4; ++mi)
#pragma unroll
                for (int ni = 0; ni < 2; ++ni) {
                    wmma::mma_sync(acc[mi][ni], aH[mi], bH[ni], acc[mi][ni]);
                    wmma::mma_sync(acc[mi][ni], aH[mi], bL[ni], acc[mi][ni]);
                    wmma::mma_sync(acc[mi][ni], aL[mi], bH[ni], acc[mi][ni]);
                }
        }
        __syncthreads();
    }

#pragma unroll
    for (int mi = 0; mi < 4; ++mi)
#pragma unroll
        for (int ni = 0; ni < 2; ++ni) {
            const int rr = bm*128 + wm*64 + mi*16;
            const int cc = bn*128 + wn*32 + ni*16;
            wmma::store_matrix_sync(C + (size_t)rr * N + cc, acc[mi][ni], N,
                                    wmma::mem_row_major);
        }
}

// ---------------------------------------------------------------------------
// Fused middle kernel (per layer): conv(4)+bias+SiLU -> x_proj -> dt_proj
// + softplus.  16 timesteps per block, 512 blocks, 256 threads.
// ---------------------------------------------------------------------------
__global__ void __launch_bounds__(256)
fused_mid_kernel(const float* __restrict__ conv_w,
                 const float* __restrict__ conv_b,
                 const float* __restrict__ xpw,
                 const float* __restrict__ dtw,
                 const float* __restrict__ dtb)
{
    __shared__ float xc_s  [16][DIv];
    __shared__ float wc_s  [48][66];
    __shared__ float xdbl_s[16][48];

    const int blk = blockIdx.x;
    const int b   = blk >> 6;
    const int t0  = (blk & 63) << 4;
    const int tid = threadIdx.x;

#pragma unroll
    for (int dd = 0; dd < 2; ++dd) {
        const int d = tid + dd * 256;
        const float* xin = g_xz + (size_t)(b * Tv) * (2*DIv) + d;
        const float4 cw4 = *(const float4*)(conv_w + d*4);
        const float  cb  = conv_b[d];
        float x0 = (t0 - 3 >= 0) ? xin[(size_t)(t0-3) * (2*DIv)] : 0.f;
        float x1 = (t0 - 2 >= 0) ? xin[(size_t)(t0-2) * (2*DIv)] : 0.f;
        float x2 = (t0 - 1 >= 0) ? xin[(size_t)(t0-1) * (2*DIv)] : 0.f;
#pragma unroll
        for (int tt = 0; tt < 16; ++tt) {
            const float x3 = xin[(size_t)(t0+tt) * (2*DIv)];
            float s = cw4.x*x0 + cw4.y*x1 + cw4.z*x2 + cw4.w*x3 + cb;
            float sl = s / (1.f + __expf(-s));
            xc_s[tt][d] = sl;
            g_xc[((size_t)(b*Tv + t0 + tt)) * DIv + d] = sl;
            x0 = x1; x1 = x2; x2 = x3;
        }
    }
    __syncthreads();

    const int tt  = tid >> 4;
    const int oth = tid & 15;
    float acc0 = 0.f, acc1 = 0.f, acc2 = 0.f;

    for (int kc = 0; kc < DIv; kc += 64) {
#pragma unroll
        for (int j = 0; j < 3; ++j) {
            const int l4 = tid * 3 + j;
            const int o  = l4 >> 4;
            const int k  = (l4 & 15) << 2;
            const float4 v = *(const float4*)(xpw + o*DIv + kc + k);
            wc_s[o][k+0] = v.x; wc_s[o][k+1] = v.y;
            wc_s[o][k+2] = v.z; wc_s[o][k+3] = v.w;
        }
        __syncthreads();
#pragma unroll 8
        for (int k = 0; k < 64; ++k) {
            const float a = xc_s[tt][kc + k];
            acc0 += a * wc_s[oth      ][k];
            acc1 += a * wc_s[oth + 16][k];
            acc2 += a * wc_s[oth + 32][k];
        }
        __syncthreads();
    }
    xdbl_s[tt][oth     ] = acc0;
    xdbl_s[tt][oth + 16] = acc1;
    xdbl_s[tt][oth + 32] = acc2;
    __syncthreads();

    {
        int idx = tid;
#pragma unroll
        for (int r = 0; r < 2; ++r, idx += 256) {
            const int tti = idx >> 5, c = idx & 31;
            g_BC[((size_t)(b*Tv + t0 + tti)) * (2*Nv) + c] = xdbl_s[tti][16 + c];
        }
    }

#pragma unroll
    for (int dd = 0; dd < 2; ++dd) {
        const int d = tid + dd * 256;
        float w[16];
        *(float4*)&w[0]  = *(const float4*)(dtw + d*16 + 0);
        *(float4*)&w[4]  = *(const float4*)(dtw + d*16 + 4);
        *(float4*)&w[8]  = *(const float4*)(dtw + d*16 + 8);
        *(float4*)&w[12] = *(const float4*)(dtw + d*16 + 12);
        const float bia = dtb[d];
#pragma unroll
        for (int tt2 = 0; tt2 < 16; ++tt2) {
            float s = bia;
#pragma unroll
            for (int r = 0; r < 16; ++r) s += xdbl_s[tt2][r] * w[r];
            float sp = fmaxf(s, 0.f) + log1pf(__expf(-fabsf(s)));
            g_dt[((size_t)(b*Tv + t0 + tt2)) * DIv + d] = sp;
        }
    }
}

// ---------------------------------------------------------------------------
// Selective scan: smem-chunked with register prefetch of the next chunk.
// grid = (32, 8), 256 threads.  Warp handles 2 channels (16 lanes each).
// ---------------------------------------------------------------------------
__global__ void __launch_bounds__(256)
scan2_kernel(const float* __restrict__ A_log, const float* __restrict__ Dp)
{
    __shared__ float s_dt[64][16];
    __shared__ float s_u [64][16];
    __shared__ float s_z [64][16];
    __shared__ float s_bc[64][32];

    const int d0   = blockIdx.x * 16;
    const int b    = blockIdx.y;
    const int tid  = threadIdx.x;
    const int warp = tid >> 5;
    const int lane = tid & 31;
    const int half = lane >> 4;
    const int n    = lane & 15;
    const int dloc = warp * 2 + half;
    const int d    = d0 + dloc;

    const float a     = -__expf(A_log[d * Nv + n]);
    const float dcoef = Dp[d];
    float h = 0.f;

    // per-thread staging coordinates
    const int stt = tid >> 4,  sdd = tid & 15;     // for dt/u/z (4 rows apart)
    const int btt = tid >> 5,  bcc = tid & 31;     // for BC     (8 rows apart)

    float r_dt[4], r_u[4], r_z[4], r_bc[8];

    // ---- prefetch chunk 0 ---------------------------------------------------
    {
        const int base = b * Tv;
#pragma unroll
        for (int i = 0; i < 4; ++i) {
            const int tt = stt + i * 16;
            r_dt[i] = g_dt[(size_t)(base + tt) * DIv + d0 + sdd];
            r_u [i] = g_xc[(size_t)(base + tt) * DIv + d0 + sdd];
            r_z [i] = g_xz[(size_t)(base + tt) * (2*DIv) + DIv + d0 + sdd];
        }
#pragma unroll
        for (int i = 0; i < 8; ++i)
            r_bc[i] = g_BC[(size_t)(base + btt + i*8) * (2*Nv) + bcc];
    }

    for (int tc = 0; tc < Tv; tc += 64) {
        const int base = b * Tv + tc;

        // ---- commit prefetched regs to smem ---------------------------------
#pragma unroll
        for (int i = 0; i < 4; ++i) {
            s_dt[stt + i*16][sdd] = r_dt[i];
            s_u [stt + i*16][sdd] = r_u [i];
            s_z [stt + i*16][sdd] = r_z [i];
        }
#pragma unroll
        for (int i = 0; i < 8; ++i)
            s_bc[btt + i*8][bcc] = r_bc[i];
        __syncthreads();

        // ---- prefetch next chunk into regs (overlaps with scan below) -------
        if (tc + 64 < Tv) {
            const int nb = base + 64;
#pragma unroll
            for (int i = 0; i < 4; ++i) {
                const int tt = stt + i * 16;
                r_dt[i] = g_dt[(size_t)(nb + tt) * DIv + d0 + sdd];
                r_u [i] = g_xc[(size_t)(nb + tt) * DIv + d0 + sdd];
                r_z [i] = g_xz[(size_t)(nb + tt) * (2*DIv) + DIv + d0 + sdd];
            }
#pragma unroll
            for (int i = 0; i < 8; ++i)
                r_bc[i] = g_BC[(size_t)(nb + btt + i*8) * (2*Nv) + bcc];
        }

        // ---- scan 64 timesteps from smem -------------------------------------
#pragma unroll 4
        for (int tt = 0; tt < 64; ++tt) {
            const float dtv = s_dt[tt][dloc];
            const float uv  = s_u [tt][dloc];
            const float bv  = s_bc[tt][n];
            const float cv  = s_bc[tt][Nv + n];

            const float dA = __expf(dtv * a);
            h = dA * h + (dtv * uv) * bv;

            float part = h * cv;
            part += __shfl_xor_sync(0xffffffffu, part, 1);
            part += __shfl_xor_sync(0xffffffffu, part, 2);
            part += __shfl_xor_sync(0xffffffffu, part, 4);
            part += __shfl_xor_sync(0xffffffffu, part, 8);

            if (n == 0) {
                const float zv = s_z[tt][dloc];
                float y = part + dcoef * uv;
                y *= zv / (1.f + __expf(-zv));
                g_y[(size_t)(base + tt) * DIv + d] = y;
            }
        }
        __syncthreads();
    }
}

// ---------------------------------------------------------------------------
// Final: LayerNorm(last token) + head.
// ---------------------------------------------------------------------------
__global__ void __launch_bounds__(256)
final_kernel(const float* __restrict__ ln_g, const float* __restrict__ ln_b,
             const float* __restrict__ head_w, const float* __restrict__ head_b,
             float* __restrict__ out)
{
    __shared__ float red[256];
    const int b = blockIdx.x, tid = threadIdx.x;
    const float v = g_h[((size_t)(b * Tv + (Tv - 1))) * DMv + tid];

    red[tid] = v; __syncthreads();
    for (int s = 128; s > 0; s >>= 1) { if (tid < s) red[tid] += red[tid + s]; __syncthreads(); }
    const float mu = red[0] * (1.f / DMv);
    __syncthreads();

    const float dv = v - mu;
    red[tid] = dv * dv; __syncthreads();
    for (int s = 128; s > 0; s >>= 1) { if (tid < s) red[tid] += red[tid + s]; __syncthreads(); }
    const float var = red[0] * (1.f / DMv);
    __syncthreads();

    const float hn = dv * rsqrtf(var + 1e-5f) * ln_g[tid] + ln_b[tid];
    red[tid] = hn * head_w[tid]; __syncthreads();
    for (int s = 128; s > 0; s >>= 1) { if (tid < s) red[tid] += red[tid + s]; __syncthreads(); }
    if (tid == 0) out[b] = red[0] + head_b[0];
}

// ---------------------------------------------------------------------------
// Host launcher
// ---------------------------------------------------------------------------
extern "C" void kernel_launch(void* const* d_in, const int* in_sizes, int n_in,
                              void* d_out, int out_size)
{
    const float* x      = (const float*)d_in[0];
    const float* proj_w = (const float*)d_in[1];
    const float* proj_b = (const float*)d_in[2];
    const float* ipw    = (const float*)d_in[3];
    const float* cw     = (const float*)d_in[4];
    const float* cb     = (const float*)d_in[5];
    const float* xpw    = (const float*)d_in[6];
    const float* dtw    = (const float*)d_in[7];
    const float* dtb    = (const float*)d_in[8];
    const float* A_log  = (const float*)d_in[9];
    const float* Dp     = (const float*)d_in[10];
    const float* opw    = (const float*)d_in[11];
    const float* ln_g   = (const float*)d_in[12];
    const float* ln_b   = (const float*)d_in[13];
    const float* head_w = (const float*)d_in[14];
    const float* head_b = (const float*)d_in[15];
    float* out = (float*)d_out;

    float *hbuf, *xzbuf, *ybuf;
    __nv_bfloat16 *whi, *wlo;
    cudaGetSymbolAddress((void**)&hbuf,  g_h);
    cudaGetSymbolAddress((void**)&xzbuf, g_xz);
    cudaGetSymbolAddress((void**)&ybuf,  g_y);
    cudaGetSymbolAddress((void**)&whi,   g_whi);
    cudaGetSymbolAddress((void**)&wlo,   g_wlo);

    __nv_bfloat16* whi_proj = whi;
    __nv_bfloat16* wlo_proj = wlo;
    __nv_bfloat16* whi_ipw  = whi + 16384;
    __nv_bfloat16* wlo_ipw  = wlo + 16384;
    __nv_bfloat16* whi_opw  = whi + 1064960;
    __nv_bfloat16* wlo_opw  = wlo + 1064960;

    // Launch 1: ipw split.  Launch 2: proj_w + opw split.
    split4_kernel<<<1024, 256>>>(ipw, whi_ipw, wlo_ipw, 262144);
    split_misc_kernel<<<528, 256>>>(proj_w, opw, whi_proj, wlo_proj,
                                    whi_opw, wlo_opw);

    dim3 grid_in(2, 64);      // N=256/128,  M=8192/128
    dim3 grid_ip(8, 64);      // N=1024/128
    dim3 grid_op(2, 64);      // N=256/128
    dim3 grid_sc(32, 8);      // channel groups x batches

    // Launch 3: input projection  h = x @ proj_w^T  (proj_b folded into
    // layer-0 in_proj A-read)   [8192,256], K=64.
    wgemm_nt_kernel<<<grid_in, 256>>>(x, (const float*)0,
                                      whi_proj, wlo_proj, hbuf, BT, DMv, Fv);

    for (int l = 0; l < Lv; ++l) {
        const size_t ipoff = (size_t)l * 262144;   // (2*DIv)*DMv
        const size_t opoff = (size_t)l * 131072;   // DMv*DIv
        const float* abias = (l == 0) ? proj_b : (const float*)0;

        // Launch 4 (profiled): in_proj  xz = (h+bias?) @ ipw^T  [8192,1024]
        wgemm_nt_kernel<<<grid_ip, 256>>>(hbuf, abias,
                                          whi_ipw + ipoff, wlo_ipw + ipoff,
                                          xzbuf, BT, 2*DIv, DMv);

        fused_mid_kernel<<<512, 256>>>(
            cw  + (size_t)l * DIv * DCv,
            cb  + (size_t)l * DIv,
            xpw + (size_t)l * (DTRv + 2*Nv) * DIv,
            dtw + (size_t)l * DIv * DTRv,
            dtb + (size_t)l * DIv);

        scan2_kernel<<<grid_sc, 256>>>(A_log + (size_t)l * DIv * Nv,
                                       Dp    + (size_t)l * DIv);

        // out_proj: h = y @ opw^T   [8192,256], K=512
        wgemm_nt_kernel<<<grid_op, 256>>>(ybuf, (const float*)0,
                                          whi_opw + opoff, wlo_opw + opoff,
                                          hbuf, BT, DMv, DIv);
    }

    final_kernel<<<Bv, 256>>>(ln_g, ln_b, head_w, head_b, out);
}

// round 8
// speedup vs baseline: 1.1110x; 1.0355x over previous
#include <cuda_runtime.h>
#include <cuda_bf16.h>
#include <mma.h>
#include <math.h>

using namespace nvcuda;

// ---------------------------------------------------------------------------
// Problem constants
// ---------------------------------------------------------------------------
#define Bv   8
#define Tv   1024
#define Fv   64
#define DMv  256
#define Lv   4
#define DIv  512          // 2*DM
#define Nv   16
#define DCv  4
#define DTRv 16           // DM/16
#define BT   (Bv*Tv)      // 8192

// ---------------------------------------------------------------------------
// Scratch (device globals; no runtime allocation allowed)
// ---------------------------------------------------------------------------
__device__ float g_h  [BT * DMv];        // hidden (fp32)
__device__ float g_xz [BT * (2*DIv)];    // in_proj output (xc_raw | z)
__device__ float g_xc [BT * DIv];        // conv+silu output (u)
__device__ float g_dt [BT * DIv];        // softplus(dt)
__device__ float g_BC [BT * (2*Nv)];     // B | C
__device__ float g_y  [BT * DIv];        // gated scan output

// split-bf16 weight buffers: proj_w[16384] | ipw[1048576] | opw[524288]
__device__ __nv_bfloat16 g_whi[1589248];
__device__ __nv_bfloat16 g_wlo[1589248];

// ---------------------------------------------------------------------------
// One-shot weight split: proj_w + ipw + opw in a single launch.
// float4 regions: proj [0,4096), ipw [4096,266240), opw [266240,397312).
// grid = 1552 x 256 covers exactly 397312 float4s.
// ---------------------------------------------------------------------------
__global__ void __launch_bounds__(256)
split_all_kernel(const float* __restrict__ proj_w,
                 const float* __restrict__ ipw,
                 const float* __restrict__ opw,
                 __nv_bfloat16* __restrict__ whi,
                 __nv_bfloat16* __restrict__ wlo)
{
    const int i = blockIdx.x * 256 + threadIdx.x;   // float4 index
    const float* src;
    int j, dst;                                      // dst in elements
    if (i < 4096)        { src = proj_w; j = i;           dst = 0; }
    else if (i < 266240) { src = ipw;    j = i - 4096;    dst = 16384; }
    else if (i < 397312) { src = opw;    j = i - 266240;  dst = 1064960; }
    else return;

    const float4 v = *(const float4*)(src + j*4);
    __nv_bfloat16* hi = whi + dst + j*4;
    __nv_bfloat16* lo = wlo + dst + j*4;
    __nv_bfloat16 h0 = __float2bfloat16(v.x);
    __nv_bfloat16 h1 = __float2bfloat16(v.y);
    __nv_bfloat16 h2 = __float2bfloat16(v.z);
    __nv_bfloat16 h3 = __float2bfloat16(v.w);
    __nv_bfloat162 a; a.x = h0; a.y = h1;
    __nv_bfloat162 b; b.x = h2; b.y = h3;
    *(__nv_bfloat162*)(hi)     = a;
    *(__nv_bfloat162*)(hi + 2) = b;
    __nv_bfloat162 c; c.x = __float2bfloat16(v.x - __bfloat162float(h0));
                      c.y = __float2bfloat16(v.y - __bfloat162float(h1));
    __nv_bfloat162 d; d.x = __float2bfloat16(v.z - __bfloat162float(h2));
                      d.y = __float2bfloat16(v.w - __bfloat162float(h3));
    *(__nv_bfloat162*)(lo)     = c;
    *(__nv_bfloat162*)(lo + 2) = d;
}

// ---------------------------------------------------------------------------
// Tensor-core GEMM, fp32 emulation via 2-term bf16 split.
// C[M,N] = (A + Abias_cols)[M,K] @ W[N,K]^T.  A fp32 split hi/lo on the fly.
// BM=64, BN=128, BK=32.  256 threads, 8 warps as 2(m) x 4(n), warp tile
// 32x32 (2x2 wmma frags).  ~90 regs -> 2 blocks/SM (forced).
// Requires M%64==0, N%128==0, K%32==0.
// ---------------------------------------------------------------------------
#define SPAD 40

__global__ void __launch_bounds__(256, 2)
wgemm_nt_kernel(const float* __restrict__ A, const float* __restrict__ Abias,
                const __nv_bfloat16* __restrict__ Whi,
                const __nv_bfloat16* __restrict__ Wlo,
                float* __restrict__ C,
                int M, int N, int K)
{
    __shared__ __align__(16) __nv_bfloat16 Ah[64*SPAD];
    __shared__ __align__(16) __nv_bfloat16 Al[64*SPAD];
    __shared__ __align__(16) __nv_bfloat16 Bh[128*SPAD];
    __shared__ __align__(16) __nv_bfloat16 Bl[128*SPAD];

    const int tid = threadIdx.x;
    const int bm  = blockIdx.y, bn = blockIdx.x;
    const int wid = tid >> 5;
    const int wm  = wid >> 2;        // 0..1  -> 32 rows each
    const int wn  = wid & 3;         // 0..3  -> 32 cols each

    wmma::fragment<wmma::accumulator, 16, 16, 16, float> acc[2][2];
#pragma unroll
    for (int mi = 0; mi < 2; ++mi)
#pragma unroll
        for (int ni = 0; ni < 2; ++ni)
            wmma::fill_fragment(acc[mi][ni], 0.0f);

    for (int k0 = 0; k0 < K; k0 += 32) {
        // ---- stage A (fp32 -> hi/lo, optional bias along K columns) --------
#pragma unroll
        for (int i = 0; i < 2; ++i) {
            const int idx = tid + i * 256;       // 0..511 float4s
            const int row = idx >> 3;            // 8 float4 per 32-float row
            const int kc  = (idx & 7) << 2;
            float4 v = *(const float4*)(A + (size_t)(bm*64 + row) * K + k0 + kc);
            if (Abias) {
                const float4 bb = *(const float4*)(Abias + k0 + kc);
                v.x += bb.x; v.y += bb.y; v.z += bb.z; v.w += bb.w;
            }
            __nv_bfloat16 h0 = __float2bfloat16(v.x);
            __nv_bfloat16 h1 = __float2bfloat16(v.y);
            __nv_bfloat16 h2 = __float2bfloat16(v.z);
            __nv_bfloat16 h3 = __float2bfloat16(v.w);
            __nv_bfloat162 ph0; ph0.x = h0; ph0.y = h1;
            __nv_bfloat162 ph1; ph1.x = h2; ph1.y = h3;
            *(__nv_bfloat162*)(Ah + row*SPAD + kc)     = ph0;
            *(__nv_bfloat162*)(Ah + row*SPAD + kc + 2) = ph1;
            __nv_bfloat162 pl0; pl0.x = __float2bfloat16(v.x - __bfloat162float(h0));
                                pl0.y = __float2bfloat16(v.y - __bfloat162float(h1));
            __nv_bfloat162 pl1; pl1.x = __float2bfloat16(v.z - __bfloat162float(h2));
                                pl1.y = __float2bfloat16(v.w - __bfloat162float(h3));
            *(__nv_bfloat162*)(Al + row*SPAD + kc)     = pl0;
            *(__nv_bfloat162*)(Al + row*SPAD + kc + 2) = pl1;
        }
        // ---- stage W tiles (bf16 direct, 8 halves per float4) ---------------
#pragma unroll
        for (int i = 0; i < 2; ++i) {
            const int idx = tid + i * 256;       // 0..511 float4s
            const int row = idx >> 2;            // 4 float4 per 32-half row
            const int kc  = (idx & 3) << 3;
            const size_t g = (size_t)(bn*128 + row) * K + k0 + kc;
            *(float4*)(Bh + row*SPAD + kc) = *(const float4*)(Whi + g);
            *(float4*)(Bl + row*SPAD + kc) = *(const float4*)(Wlo + g);
        }
        __syncthreads();

#pragma unroll
        for (int ks = 0; ks < 32; ks += 16) {
            wmma::fragment<wmma::matrix_b, 16, 16, 16, __nv_bfloat16, wmma::col_major> bH[2], bL[2];
#pragma unroll
            for (int ni = 0; ni < 2; ++ni) {
                const int rr = wn*32 + ni*16;
                wmma::load_matrix_sync(bH[ni], Bh + rr*SPAD + ks, SPAD);
                wmma::load_matrix_sync(bL[ni], Bl + rr*SPAD + ks, SPAD);
            }
#pragma unroll
            for (int mi = 0; mi < 2; ++mi) {
                wmma::fragment<wmma::matrix_a, 16, 16, 16, __nv_bfloat16, wmma::row_major> aH, aL;
                const int rr = wm*32 + mi*16;
                wmma::load_matrix_sync(aH, Ah + rr*SPAD + ks, SPAD);
                wmma::load_matrix_sync(aL, Al + rr*SPAD + ks, SPAD);
#pragma unroll
                for (int ni = 0; ni < 2; ++ni) {
                    wmma::mma_sync(acc[mi][ni], aH, bH[ni], acc[mi][ni]);
                    wmma::mma_sync(acc[mi][ni], aH, bL[ni], acc[mi][ni]);
                    wmma::mma_sync(acc[mi][ni], aL, bH[ni], acc[mi][ni]);
                }
            }
        }
        __syncthreads();
    }

#pragma unroll
    for (int mi = 0; mi < 2; ++mi)
#pragma unroll
        for (int ni = 0; ni < 2; ++ni) {
            const int rr = bm*64 + wm*32 + mi*16;
            const int cc = bn*128 + wn*32 + ni*16;
            wmma::store_matrix_sync(C + (size_t)rr * N + cc, acc[mi][ni], N,
                                    wmma::mem_row_major);
        }
}

// ---------------------------------------------------------------------------
// Fused middle kernel (per layer): conv(4)+bias+SiLU -> x_proj -> dt_proj
// + softplus.  16 timesteps per block, 512 blocks, 256 threads.
// ---------------------------------------------------------------------------
__global__ void __launch_bounds__(256)
fused_mid_kernel(const float* __restrict__ conv_w,
                 const float* __restrict__ conv_b,
                 const float* __restrict__ xpw,
                 const float* __restrict__ dtw,
                 const float* __restrict__ dtb)
{
    __shared__ float xc_s  [16][DIv];
    __shared__ float wc_s  [48][66];
    __shared__ float xdbl_s[16][48];

    const int blk = blockIdx.x;
    const int b   = blk >> 6;
    const int t0  = (blk & 63) << 4;
    const int tid = threadIdx.x;

#pragma unroll
    for (int dd = 0; dd < 2; ++dd) {
        const int d = tid + dd * 256;
        const float* xin = g_xz + (size_t)(b * Tv) * (2*DIv) + d;
        const float4 cw4 = *(const float4*)(conv_w + d*4);
        const float  cb  = conv_b[d];
        float x0 = (t0 - 3 >= 0) ? xin[(size_t)(t0-3) * (2*DIv)] : 0.f;
        float x1 = (t0 - 2 >= 0) ? xin[(size_t)(t0-2) * (2*DIv)] : 0.f;
        float x2 = (t0 - 1 >= 0) ? xin[(size_t)(t0-1) * (2*DIv)] : 0.f;
#pragma unroll
        for (int tt = 0; tt < 16; ++tt) {
            const float x3 = xin[(size_t)(t0+tt) * (2*DIv)];
            float s = cw4.x*x0 + cw4.y*x1 + cw4.z*x2 + cw4.w*x3 + cb;
            float sl = s / (1.f + __expf(-s));
            xc_s[tt][d] = sl;
            g_xc[((size_t)(b*Tv + t0 + tt)) * DIv + d] = sl;
            x0 = x1; x1 = x2; x2 = x3;
        }
    }
    __syncthreads();

    const int tt  = tid >> 4;
    const int oth = tid & 15;
    float acc0 = 0.f, acc1 = 0.f, acc2 = 0.f;

    for (int kc = 0; kc < DIv; kc += 64) {
#pragma unroll
        for (int j = 0; j < 3; ++j) {
            const int l4 = tid * 3 + j;
            const int o  = l4 >> 4;
            const int k  = (l4 & 15) << 2;
            const float4 v = *(const float4*)(xpw + o*DIv + kc + k);
            wc_s[o][k+0] = v.x; wc_s[o][k+1] = v.y;
            wc_s[o][k+2] = v.z; wc_s[o][k+3] = v.w;
        }
        __syncthreads();
#pragma unroll 8
        for (int k = 0; k < 64; ++k) {
            const float a = xc_s[tt][kc + k];
            acc0 += a * wc_s[oth      ][k];
            acc1 += a * wc_s[oth + 16][k];
            acc2 += a * wc_s[oth + 32][k];
        }
        __syncthreads();
    }
    xdbl_s[tt][oth     ] = acc0;
    xdbl_s[tt][oth + 16] = acc1;
    xdbl_s[tt][oth + 32] = acc2;
    __syncthreads();

    {
        int idx = tid;
#pragma unroll
        for (int r = 0; r < 2; ++r, idx += 256) {
            const int tti = idx >> 5, c = idx & 31;
            g_BC[((size_t)(b*Tv + t0 + tti)) * (2*Nv) + c] = xdbl_s[tti][16 + c];
        }
    }

#pragma unroll
    for (int dd = 0; dd < 2; ++dd) {
        const int d = tid + dd * 256;
        float w[16];
        *(float4*)&w[0]  = *(const float4*)(dtw + d*16 + 0);
        *(float4*)&w[4]  = *(const float4*)(dtw + d*16 + 4);
        *(float4*)&w[8]  = *(const float4*)(dtw + d*16 + 8);
        *(float4*)&w[12] = *(const float4*)(dtw + d*16 + 12);
        const float bia = dtb[d];
#pragma unroll
        for (int tt2 = 0; tt2 < 16; ++tt2) {
            float s = bia;
#pragma unroll
            for (int r = 0; r < 16; ++r) s += xdbl_s[tt2][r] * w[r];
            float sp = fmaxf(s, 0.f) + log1pf(__expf(-fabsf(s)));
            g_dt[((size_t)(b*Tv + t0 + tt2)) * DIv + d] = sp;
        }
    }
}

// ---------------------------------------------------------------------------
// Selective scan: smem-chunked with register prefetch of the next chunk.
// grid = (32, 8), 256 threads.
// ---------------------------------------------------------------------------
__global__ void __launch_bounds__(256)
scan2_kernel(const float* __restrict__ A_log, const float* __restrict__ Dp)
{
    __shared__ float s_dt[64][16];
    __shared__ float s_u [64][16];
    __shared__ float s_z [64][16];
    __shared__ float s_bc[64][32];

    const int d0   = blockIdx.x * 16;
    const int b    = blockIdx.y;
    const int tid  = threadIdx.x;
    const int warp = tid >> 5;
    const int lane = tid & 31;
    const int half = lane >> 4;
    const int n    = lane & 15;
    const int dloc = warp * 2 + half;
    const int d    = d0 + dloc;

    const float a     = -__expf(A_log[d * Nv + n]);
    const float dcoef = Dp[d];
    float h = 0.f;

    const int stt = tid >> 4,  sdd = tid & 15;
    const int btt = tid >> 5,  bcc = tid & 31;

    float r_dt[4], r_u[4], r_z[4], r_bc[8];

    {
        const int base = b * Tv;
#pragma unroll
        for (int i = 0; i < 4; ++i) {
            const int tt = stt + i * 16;
            r_dt[i] = g_dt[(size_t)(base + tt) * DIv + d0 + sdd];
            r_u [i] = g_xc[(size_t)(base + tt) * DIv + d0 + sdd];
            r_z [i] = g_xz[(size_t)(base + tt) * (2*DIv) + DIv + d0 + sdd];
        }
#pragma unroll
        for (int i = 0; i < 8; ++i)
            r_bc[i] = g_BC[(size_t)(base + btt + i*8) * (2*Nv) + bcc];
    }

    for (int tc = 0; tc < Tv; tc += 64) {
        const int base = b * Tv + tc;

#pragma unroll
        for (int i = 0; i < 4; ++i) {
            s_dt[stt + i*16][sdd] = r_dt[i];
            s_u [stt + i*16][sdd] = r_u [i];
            s_z [stt + i*16][sdd] = r_z [i];
        }
#pragma unroll
        for (int i = 0; i < 8; ++i)
            s_bc[btt + i*8][bcc] = r_bc[i];
        __syncthreads();

        if (tc + 64 < Tv) {
            const int nb = base + 64;
#pragma unroll
            for (int i = 0; i < 4; ++i) {
                const int tt = stt + i * 16;
                r_dt[i] = g_dt[(size_t)(nb + tt) * DIv + d0 + sdd];
                r_u [i] = g_xc[(size_t)(nb + tt) * DIv + d0 + sdd];
                r_z [i] = g_xz[(size_t)(nb + tt) * (2*DIv) + DIv + d0 + sdd];
            }
#pragma unroll
            for (int i = 0; i < 8; ++i)
                r_bc[i] = g_BC[(size_t)(nb + btt + i*8) * (2*Nv) + bcc];
        }

#pragma unroll 4
        for (int tt = 0; tt < 64; ++tt) {
            const float dtv = s_dt[tt][dloc];
            const float uv  = s_u [tt][dloc];
            const float bv  = s_bc[tt][n];
            const float cv  = s_bc[tt][Nv + n];

            const float dA = __expf(dtv * a);
            h = dA * h + (dtv * uv) * bv;

            float part = h * cv;
            part += __shfl_xor_sync(0xffffffffu, part, 1);
            part += __shfl_xor_sync(0xffffffffu, part, 2);
            part += __shfl_xor_sync(0xffffffffu, part, 4);
            part += __shfl_xor_sync(0xffffffffu, part, 8);

            if (n == 0) {
                const float zv = s_z[tt][dloc];
                float y = part + dcoef * uv;
                y *= zv / (1.f + __expf(-zv));
                g_y[(size_t)(base + tt) * DIv + d] = y;
            }
        }
        __syncthreads();
    }
}

// ---------------------------------------------------------------------------
// Final: LayerNorm(last token) + head.
// ---------------------------------------------------------------------------
__global__ void __launch_bounds__(256)
final_kernel(const float* __restrict__ ln_g, const float* __restrict__ ln_b,
             const float* __restrict__ head_w, const float* __restrict__ head_b,
             float* __restrict__ out)
{
    __shared__ float red[256];
    const int b = blockIdx.x, tid = threadIdx.x;
    const float v = g_h[((size_t)(b * Tv + (Tv - 1))) * DMv + tid];

    red[tid] = v; __syncthreads();
    for (int s = 128; s > 0; s >>= 1) { if (tid < s) red[tid] += red[tid + s]; __syncthreads(); }
    const float mu = red[0] * (1.f / DMv);
    __syncthreads();

    const float dv = v - mu;
    red[tid] = dv * dv; __syncthreads();
    for (int s = 128; s > 0; s >>= 1) { if (tid < s) red[tid] += red[tid + s]; __syncthreads(); }
    const float var = red[0] * (1.f / DMv);
    __syncthreads();

    const float hn = dv * rsqrtf(var + 1e-5f) * ln_g[tid] + ln_b[tid];
    red[tid] = hn * head_w[tid]; __syncthreads();
    for (int s = 128; s > 0; s >>= 1) { if (tid < s) red[tid] += red[tid + s]; __syncthreads(); }
    if (tid == 0) out[b] = red[0] + head_b[0];
}

// ---------------------------------------------------------------------------
// Host launcher
// ---------------------------------------------------------------------------
extern "C" void kernel_launch(void* const* d_in, const int* in_sizes, int n_in,
                              void* d_out, int out_size)
{
    const float* x      = (const float*)d_in[0];
    const float* proj_w = (const float*)d_in[1];
    const float* proj_b = (const float*)d_in[2];
    const float* ipw    = (const float*)d_in[3];
    const float* cw     = (const float*)d_in[4];
    const float* cb     = (const float*)d_in[5];
    const float* xpw    = (const float*)d_in[6];
    const float* dtw    = (const float*)d_in[7];
    const float* dtb    = (const float*)d_in[8];
    const float* A_log  = (const float*)d_in[9];
    const float* Dp     = (const float*)d_in[10];
    const float* opw    = (const float*)d_in[11];
    const float* ln_g   = (const float*)d_in[12];
    const float* ln_b   = (const float*)d_in[13];
    const float* head_w = (const float*)d_in[14];
    const float* head_b = (const float*)d_in[15];
    float* out = (float*)d_out;

    float *hbuf, *xzbuf, *ybuf;
    __nv_bfloat16 *whi, *wlo;
    cudaGetSymbolAddress((void**)&hbuf,  g_h);
    cudaGetSymbolAddress((void**)&xzbuf, g_xz);
    cudaGetSymbolAddress((void**)&ybuf,  g_y);
    cudaGetSymbolAddress((void**)&whi,   g_whi);
    cudaGetSymbolAddress((void**)&wlo,   g_wlo);

    __nv_bfloat16* whi_proj = whi;
    __nv_bfloat16* wlo_proj = wlo;
    __nv_bfloat16* whi_ipw  = whi + 16384;
    __nv_bfloat16* wlo_ipw  = wlo + 16384;
    __nv_bfloat16* whi_opw  = whi + 1064960;
    __nv_bfloat16* wlo_opw  = wlo + 1064960;

    // Launch 1: all weight splits in one kernel.
    split_all_kernel<<<1552, 256>>>(proj_w, ipw, opw, whi, wlo);

    dim3 grid_in(2, 128);     // N=256/128,  M=8192/64
    dim3 grid_ip(8, 128);     // N=1024/128
    dim3 grid_op(2, 128);     // N=256/128
    dim3 grid_sc(32, 8);      // channel groups x batches

    // Launch 2: input projection  h = x @ proj_w^T  [8192,256], K=64
    // (proj_b folded into layer-0 in_proj A-read)
    wgemm_nt_kernel<<<grid_in, 256>>>(x, (const float*)0,
                                      whi_proj, wlo_proj, hbuf, BT, DMv, Fv);

    for (int l = 0; l < Lv; ++l) {
        const size_t ipoff = (size_t)l * 262144;   // (2*DIv)*DMv
        const size_t opoff = (size_t)l * 131072;   // DMv*DIv
        const float* abias = (l == 0) ? proj_b : (const float*)0;

        // Launch 3: in_proj  xz = (h+bias?) @ ipw^T  [8192,1024], K=256
        wgemm_nt_kernel<<<grid_ip, 256>>>(hbuf, abias,
                                          whi_ipw + ipoff, wlo_ipw + ipoff,
                                          xzbuf, BT, 2*DIv, DMv);

        // Launch 4 (profiled, l==0): fused conv/x_proj/dt_proj
        fused_mid_kernel<<<512, 256>>>(
            cw  + (size_t)l * DIv * DCv,
            cb  + (size_t)l * DIv,
            xpw + (size_t)l * (DTRv + 2*Nv) * DIv,
            dtw + (size_t)l * DIv * DTRv,
            dtb + (size_t)l * DIv);

        scan2_kernel<<<grid_sc, 256>>>(A_log + (size_t)l * DIv * Nv,
                                       Dp    + (size_t)l * DIv);

        // out_proj: h = y @ opw^T   [8192,256], K=512
        wgemm_nt_kernel<<<grid_op, 256>>>(ybuf, (const float*)0,
                                          whi_opw + opoff, wlo_opw + opoff,
                                          hbuf, BT, DMv, DIv);
    }

    final_kernel<<<Bv, 256>>>(ln_g, ln_b, head_w, head_b, out);
}

// round 9
// speedup vs baseline: 1.3230x; 1.1909x over previous
#include <cuda_runtime.h>
#include <cuda_bf16.h>
#include <mma.h>
#include <math.h>

using namespace nvcuda;

// ---------------------------------------------------------------------------
// Problem constants
// ---------------------------------------------------------------------------
#define Bv   8
#define Tv   1024
#define Fv   64
#define DMv  256
#define Lv   4
#define DIv  512          // 2*DM
#define Nv   16
#define DCv  4
#define DTRv 16           // DM/16
#define BT   (Bv*Tv)      // 8192
#define NCH  8            // scan chunks
#define CHT  128          // timesteps per chunk

// ---------------------------------------------------------------------------
// Scratch (device globals; no runtime allocation allowed)
// ---------------------------------------------------------------------------
__device__ float g_h  [BT * DMv];        // hidden (fp32)
__device__ float g_xz [BT * (2*DIv)];    // in_proj output (xc_raw | z)
__device__ float g_xc [BT * DIv];        // conv+silu output (u)
__device__ float g_dt [BT * DIv];        // softplus(dt)
__device__ float g_BC [BT * (2*Nv)];     // B | C
__device__ float g_y  [BT * DIv];        // gated scan output

// chunked-scan state: layout [b][d][n][c], c contiguous
__device__ float g_chP[Bv * DIv * Nv * NCH];   // 2 MB
__device__ float g_chH[Bv * DIv * Nv * NCH];   // 2 MB (end-states, then starts)

// split-bf16 weight buffers: proj_w[16384] | ipw[1048576] | opw[524288]
__device__ __nv_bfloat16 g_whi[1589248];
__device__ __nv_bfloat16 g_wlo[1589248];

// ---------------------------------------------------------------------------
// Weight splits
// ---------------------------------------------------------------------------
__global__ void __launch_bounds__(256)
split_ipw_kernel(const float* __restrict__ ipw,
                 __nv_bfloat16* __restrict__ whi, __nv_bfloat16* __restrict__ wlo)
{
    const int i = blockIdx.x * 256 + threadIdx.x;   // 0..262143 float4s
    const float4 v = *(const float4*)(ipw + i*4);
    __nv_bfloat16* hi = whi + 16384 + i*4;
    __nv_bfloat16* lo = wlo + 16384 + i*4;
    __nv_bfloat16 h0 = __float2bfloat16(v.x);
    __nv_bfloat16 h1 = __float2bfloat16(v.y);
    __nv_bfloat16 h2 = __float2bfloat16(v.z);
    __nv_bfloat16 h3 = __float2bfloat16(v.w);
    __nv_bfloat162 a; a.x = h0; a.y = h1;
    __nv_bfloat162 b; b.x = h2; b.y = h3;
    *(__nv_bfloat162*)(hi)     = a;
    *(__nv_bfloat162*)(hi + 2) = b;
    __nv_bfloat162 c; c.x = __float2bfloat16(v.x - __bfloat162float(h0));
                      c.y = __float2bfloat16(v.y - __bfloat162float(h1));
    __nv_bfloat162 d; d.x = __float2bfloat16(v.z - __bfloat162float(h2));
                      d.y = __float2bfloat16(v.w - __bfloat162float(h3));
    *(__nv_bfloat162*)(lo)     = c;
    *(__nv_bfloat162*)(lo + 2) = d;
}

__global__ void __launch_bounds__(256)
split_misc_kernel(const float* __restrict__ proj_w, const float* __restrict__ opw,
                  __nv_bfloat16* __restrict__ whi, __nv_bfloat16* __restrict__ wlo)
{
    const int i = blockIdx.x * 256 + threadIdx.x;   // 0..135167
    const float* src;
    int j, dst;
    if (i < 4096)        { src = proj_w; j = i;          dst = 0; }
    else if (i < 135168) { src = opw;    j = i - 4096;   dst = 1064960; }
    else return;
    const float4 v = *(const float4*)(src + j*4);
    __nv_bfloat16* hi = whi + dst + j*4;
    __nv_bfloat16* lo = wlo + dst + j*4;
    __nv_bfloat16 h0 = __float2bfloat16(v.x);
    __nv_bfloat16 h1 = __float2bfloat16(v.y);
    __nv_bfloat16 h2 = __float2bfloat16(v.z);
    __nv_bfloat16 h3 = __float2bfloat16(v.w);
    __nv_bfloat162 a; a.x = h0; a.y = h1;
    __nv_bfloat162 b; b.x = h2; b.y = h3;
    *(__nv_bfloat162*)(hi)     = a;
    *(__nv_bfloat162*)(hi + 2) = b;
    __nv_bfloat162 c; c.x = __float2bfloat16(v.x - __bfloat162float(h0));
                      c.y = __float2bfloat16(v.y - __bfloat162float(h1));
    __nv_bfloat162 d; d.x = __float2bfloat16(v.z - __bfloat162float(h2));
                      d.y = __float2bfloat16(v.w - __bfloat162float(h3));
    *(__nv_bfloat162*)(lo)     = c;
    *(__nv_bfloat162*)(lo + 2) = d;
}

// ---------------------------------------------------------------------------
// Tensor-core GEMM, fp32 emulation via 2-term bf16 split (unchanged from R8).
// ---------------------------------------------------------------------------
#define SPAD 40

__global__ void __launch_bounds__(256, 2)
wgemm_nt_kernel(const float* __restrict__ A, const float* __restrict__ Abias,
                const __nv_bfloat16* __restrict__ Whi,
                const __nv_bfloat16* __restrict__ Wlo,
                float* __restrict__ C,
                int M, int N, int K)
{
    __shared__ __align__(16) __nv_bfloat16 Ah[64*SPAD];
    __shared__ __align__(16) __nv_bfloat16 Al[64*SPAD];
    __shared__ __align__(16) __nv_bfloat16 Bh[128*SPAD];
    __shared__ __align__(16) __nv_bfloat16 Bl[128*SPAD];

    const int tid = threadIdx.x;
    const int bm  = blockIdx.y, bn = blockIdx.x;
    const int wid = tid >> 5;
    const int wm  = wid >> 2;
    const int wn  = wid & 3;

    wmma::fragment<wmma::accumulator, 16, 16, 16, float> acc[2][2];
#pragma unroll
    for (int mi = 0; mi < 2; ++mi)
#pragma unroll
        for (int ni = 0; ni < 2; ++ni)
            wmma::fill_fragment(acc[mi][ni], 0.0f);

    for (int k0 = 0; k0 < K; k0 += 32) {
#pragma unroll
        for (int i = 0; i < 2; ++i) {
            const int idx = tid + i * 256;
            const int row = idx >> 3;
            const int kc  = (idx & 7) << 2;
            float4 v = *(const float4*)(A + (size_t)(bm*64 + row) * K + k0 + kc);
            if (Abias) {
                const float4 bb = *(const float4*)(Abias + k0 + kc);
                v.x += bb.x; v.y += bb.y; v.z += bb.z; v.w += bb.w;
            }
            __nv_bfloat16 h0 = __float2bfloat16(v.x);
            __nv_bfloat16 h1 = __float2bfloat16(v.y);
            __nv_bfloat16 h2 = __float2bfloat16(v.z);
            __nv_bfloat16 h3 = __float2bfloat16(v.w);
            __nv_bfloat162 ph0; ph0.x = h0; ph0.y = h1;
            __nv_bfloat162 ph1; ph1.x = h2; ph1.y = h3;
            *(__nv_bfloat162*)(Ah + row*SPAD + kc)     = ph0;
            *(__nv_bfloat162*)(Ah + row*SPAD + kc + 2) = ph1;
            __nv_bfloat162 pl0; pl0.x = __float2bfloat16(v.x - __bfloat162float(h0));
                                pl0.y = __float2bfloat16(v.y - __bfloat162float(h1));
            __nv_bfloat162 pl1; pl1.x = __float2bfloat16(v.z - __bfloat162float(h2));
                                pl1.y = __float2bfloat16(v.w - __bfloat162float(h3));
            *(__nv_bfloat162*)(Al + row*SPAD + kc)     = pl0;
            *(__nv_bfloat162*)(Al + row*SPAD + kc + 2) = pl1;
        }
#pragma unroll
        for (int i = 0; i < 2; ++i) {
            const int idx = tid + i * 256;
            const int row = idx >> 2;
            const int kc  = (idx & 3) << 3;
            const size_t g = (size_t)(bn*128 + row) * K + k0 + kc;
            *(float4*)(Bh + row*SPAD + kc) = *(const float4*)(Whi + g);
            *(float4*)(Bl + row*SPAD + kc) = *(const float4*)(Wlo + g);
        }
        __syncthreads();

#pragma unroll
        for (int ks = 0; ks < 32; ks += 16) {
            wmma::fragment<wmma::matrix_b, 16, 16, 16, __nv_bfloat16, wmma::col_major> bH[2], bL[2];
#pragma unroll
            for (int ni = 0; ni < 2; ++ni) {
                const int rr = wn*32 + ni*16;
                wmma::load_matrix_sync(bH[ni], Bh + rr*SPAD + ks, SPAD);
                wmma::load_matrix_sync(bL[ni], Bl + rr*SPAD + ks, SPAD);
            }
#pragma unroll
            for (int mi = 0; mi < 2; ++mi) {
                wmma::fragment<wmma::matrix_a, 16, 16, 16, __nv_bfloat16, wmma::row_major> aH, aL;
                const int rr = wm*32 + mi*16;
                wmma::load_matrix_sync(aH, Ah + rr*SPAD + ks, SPAD);
                wmma::load_matrix_sync(aL, Al + rr*SPAD + ks, SPAD);
#pragma unroll
                for (int ni = 0; ni < 2; ++ni) {
                    wmma::mma_sync(acc[mi][ni], aH, bH[ni], acc[mi][ni]);
                    wmma::mma_sync(acc[mi][ni], aH, bL[ni], acc[mi][ni]);
                    wmma::mma_sync(acc[mi][ni], aL, bH[ni], acc[mi][ni]);
                }
            }
        }
        __syncthreads();
    }

#pragma unroll
    for (int mi = 0; mi < 2; ++mi)
#pragma unroll
        for (int ni = 0; ni < 2; ++ni) {
            const int rr = bm*64 + wm*32 + mi*16;
            const int cc = bn*128 + wn*32 + ni*16;
            wmma::store_matrix_sync(C + (size_t)rr * N + cc, acc[mi][ni], N,
                                    wmma::mem_row_major);
        }
}

// ---------------------------------------------------------------------------
// Fused middle kernel (unchanged).
// ---------------------------------------------------------------------------
__global__ void __launch_bounds__(256)
fused_mid_kernel(const float* __restrict__ conv_w,
                 const float* __restrict__ conv_b,
                 const float* __restrict__ xpw,
                 const float* __restrict__ dtw,
                 const float* __restrict__ dtb)
{
    __shared__ float xc_s  [16][DIv];
    __shared__ float wc_s  [48][66];
    __shared__ float xdbl_s[16][48];

    const int blk = blockIdx.x;
    const int b   = blk >> 6;
    const int t0  = (blk & 63) << 4;
    const int tid = threadIdx.x;

#pragma unroll
    for (int dd = 0; dd < 2; ++dd) {
        const int d = tid + dd * 256;
        const float* xin = g_xz + (size_t)(b * Tv) * (2*DIv) + d;
        const float4 cw4 = *(const float4*)(conv_w + d*4);
        const float  cb  = conv_b[d];
        float x0 = (t0 - 3 >= 0) ? xin[(size_t)(t0-3) * (2*DIv)] : 0.f;
        float x1 = (t0 - 2 >= 0) ? xin[(size_t)(t0-2) * (2*DIv)] : 0.f;
        float x2 = (t0 - 1 >= 0) ? xin[(size_t)(t0-1) * (2*DIv)] : 0.f;
#pragma unroll
        for (int tt = 0; tt < 16; ++tt) {
            const float x3 = xin[(size_t)(t0+tt) * (2*DIv)];
            float s = cw4.x*x0 + cw4.y*x1 + cw4.z*x2 + cw4.w*x3 + cb;
            float sl = s / (1.f + __expf(-s));
            xc_s[tt][d] = sl;
            g_xc[((size_t)(b*Tv + t0 + tt)) * DIv + d] = sl;
            x0 = x1; x1 = x2; x2 = x3;
        }
    }
    __syncthreads();

    const int tt  = tid >> 4;
    const int oth = tid & 15;
    float acc0 = 0.f, acc1 = 0.f, acc2 = 0.f;

    for (int kc = 0; kc < DIv; kc += 64) {
#pragma unroll
        for (int j = 0; j < 3; ++j) {
            const int l4 = tid * 3 + j;
            const int o  = l4 >> 4;
            const int k  = (l4 & 15) << 2;
            const float4 v = *(const float4*)(xpw + o*DIv + kc + k);
            wc_s[o][k+0] = v.x; wc_s[o][k+1] = v.y;
            wc_s[o][k+2] = v.z; wc_s[o][k+3] = v.w;
        }
        __syncthreads();
#pragma unroll 8
        for (int k = 0; k < 64; ++k) {
            const float a = xc_s[tt][kc + k];
            acc0 += a * wc_s[oth      ][k];
            acc1 += a * wc_s[oth + 16][k];
            acc2 += a * wc_s[oth + 32][k];
        }
        __syncthreads();
    }
    xdbl_s[tt][oth     ] = acc0;
    xdbl_s[tt][oth + 16] = acc1;
    xdbl_s[tt][oth + 32] = acc2;
    __syncthreads();

    {
        int idx = tid;
#pragma unroll
        for (int r = 0; r < 2; ++r, idx += 256) {
            const int tti = idx >> 5, c = idx & 31;
            g_BC[((size_t)(b*Tv + t0 + tti)) * (2*Nv) + c] = xdbl_s[tti][16 + c];
        }
    }

#pragma unroll
    for (int dd = 0; dd < 2; ++dd) {
        const int d = tid + dd * 256;
        float w[16];
        *(float4*)&w[0]  = *(const float4*)(dtw + d*16 + 0);
        *(float4*)&w[4]  = *(const float4*)(dtw + d*16 + 4);
        *(float4*)&w[8]  = *(const float4*)(dtw + d*16 + 8);
        *(float4*)&w[12] = *(const float4*)(dtw + d*16 + 12);
        const float bia = dtb[d];
#pragma unroll
        for (int tt2 = 0; tt2 < 16; ++tt2) {
            float s = bia;
#pragma unroll
            for (int r = 0; r < 16; ++r) s += xdbl_s[tt2][r] * w[r];
            float sp = fmaxf(s, 0.f) + log1pf(__expf(-fabsf(s)));
            g_dt[((size_t)(b*Tv + t0 + tt2)) * DIv + d] = sp;
        }
    }
}

// ---------------------------------------------------------------------------
// Scan pass 1: per-chunk (P = prod dA, H = end state from h0=0).
// grid (32, 8, 8) = (dgroup, batch, chunk), 256 threads.
// ---------------------------------------------------------------------------
__global__ void __launch_bounds__(256)
scan_pass1_kernel(const float* __restrict__ A_log)
{
    __shared__ float s_dt[64][16];
    __shared__ float s_u [64][16];
    __shared__ float s_b [64][16];

    const int d0   = blockIdx.x * 16;
    const int b    = blockIdx.y;
    const int ch   = blockIdx.z;
    const int tid  = threadIdx.x;
    const int warp = tid >> 5;
    const int lane = tid & 31;
    const int half = lane >> 4;
    const int n    = lane & 15;
    const int dloc = warp * 2 + half;
    const int d    = d0 + dloc;

    const float a = -__expf(A_log[d * Nv + n]);
    float h = 0.f, P = 1.f;

    for (int sc = 0; sc < 2; ++sc) {
        const int base = b * Tv + ch * CHT + sc * 64;
#pragma unroll
        for (int i = 0; i < 4; ++i) {
            const int idx = tid + i * 256;
            const int tt  = idx >> 4;
            const int dd  = idx & 15;
            s_dt[tt][dd] = g_dt[(size_t)(base + tt) * DIv + d0 + dd];
            s_u [tt][dd] = g_xc[(size_t)(base + tt) * DIv + d0 + dd];
            s_b [tt][dd] = g_BC[(size_t)(base + tt) * (2*Nv) + dd];
        }
        __syncthreads();
#pragma unroll 4
        for (int tt = 0; tt < 64; ++tt) {
            const float dtv = s_dt[tt][dloc];
            const float uv  = s_u [tt][dloc];
            const float bv  = s_b [tt][n];
            const float dA  = __expf(dtv * a);
            h = dA * h + (dtv * uv) * bv;
            P *= dA;
        }
        __syncthreads();
    }

    const size_t o = (((size_t)b * DIv + d) * Nv + n) * NCH + ch;
    g_chP[o] = P;
    g_chH[o] = h;
}

// ---------------------------------------------------------------------------
// Prefix over chunks: S(c) = P(c-1) S(c-1) + H(c-1); overwrite g_chH with S.
// 65536 threads (one per (b,d,n)).
// ---------------------------------------------------------------------------
__global__ void __launch_bounds__(256)
scan_prefix_kernel()
{
    const int i = blockIdx.x * 256 + threadIdx.x;   // 0..65535
    const size_t base = (size_t)i * NCH;
    float4 P0 = *(float4*)(g_chP + base);
    float4 P1 = *(float4*)(g_chP + base + 4);
    float4 H0 = *(float4*)(g_chH + base);
    float4 H1 = *(float4*)(g_chH + base + 4);
    float4 S0, S1;
    float h = 0.f;
    S0.x = h; h = P0.x*h + H0.x;
    S0.y = h; h = P0.y*h + H0.y;
    S0.z = h; h = P0.z*h + H0.z;
    S0.w = h; h = P0.w*h + H0.w;
    S1.x = h; h = P1.x*h + H1.x;
    S1.y = h; h = P1.y*h + H1.y;
    S1.z = h; h = P1.z*h + H1.z;
    S1.w = h;
    *(float4*)(g_chH + base)     = S0;
    *(float4*)(g_chH + base + 4) = S1;
}

// ---------------------------------------------------------------------------
// Scan pass 2: full scan within chunk, seeded with S(c); emits gated y.
// grid (32, 8, 8), 256 threads.
// ---------------------------------------------------------------------------
__global__ void __launch_bounds__(256)
scan_pass2_kernel(const float* __restrict__ A_log, const float* __restrict__ Dp)
{
    __shared__ float s_dt[64][16];
    __shared__ float s_u [64][16];
    __shared__ float s_z [64][16];
    __shared__ float s_bc[64][32];

    const int d0   = blockIdx.x * 16;
    const int b    = blockIdx.y;
    const int ch   = blockIdx.z;
    const int tid  = threadIdx.x;
    const int warp = tid >> 5;
    const int lane = tid & 31;
    const int half = lane >> 4;
    const int n    = lane & 15;
    const int dloc = warp * 2 + half;
    const int d    = d0 + dloc;

    const float a     = -__expf(A_log[d * Nv + n]);
    const float dcoef = Dp[d];
    float h = g_chH[(((size_t)b * DIv + d) * Nv + n) * NCH + ch];

    for (int sc = 0; sc < 2; ++sc) {
        const int base = b * Tv + ch * CHT + sc * 64;
#pragma unroll
        for (int i = 0; i < 4; ++i) {
            const int idx = tid + i * 256;
            const int tt  = idx >> 4;
            const int dd  = idx & 15;
            s_dt[tt][dd] = g_dt[(size_t)(base + tt) * DIv + d0 + dd];
            s_u [tt][dd] = g_xc[(size_t)(base + tt) * DIv + d0 + dd];
            s_z [tt][dd] = g_xz[(size_t)(base + tt) * (2*DIv) + DIv + d0 + dd];
        }
#pragma unroll
        for (int i = 0; i < 8; ++i) {
            const int idx = tid + i * 256;
            const int tt  = idx >> 5;
            const int c   = idx & 31;
            s_bc[tt][c] = g_BC[(size_t)(base + tt) * (2*Nv) + c];
        }
        __syncthreads();

#pragma unroll 4
        for (int tt = 0; tt < 64; ++tt) {
            const float dtv = s_dt[tt][dloc];
            const float uv  = s_u [tt][dloc];
            const float bv  = s_bc[tt][n];
            const float cv  = s_bc[tt][Nv + n];

            const float dA = __expf(dtv * a);
            h = dA * h + (dtv * uv) * bv;

            float part = h * cv;
            part += __shfl_xor_sync(0xffffffffu, part, 1);
            part += __shfl_xor_sync(0xffffffffu, part, 2);
            part += __shfl_xor_sync(0xffffffffu, part, 4);
            part += __shfl_xor_sync(0xffffffffu, part, 8);

            if (n == 0) {
                const float zv = s_z[tt][dloc];
                float y = part + dcoef * uv;
                y *= zv / (1.f + __expf(-zv));
                g_y[(size_t)(base + tt) * DIv + d] = y;
            }
        }
        __syncthreads();
    }
}

// ---------------------------------------------------------------------------
// Final: LayerNorm(last token) + head.
// ---------------------------------------------------------------------------
__global__ void __launch_bounds__(256)
final_kernel(const float* __restrict__ ln_g, const float* __restrict__ ln_b,
             const float* __restrict__ head_w, const float* __restrict__ head_b,
             float* __restrict__ out)
{
    __shared__ float red[256];
    const int b = blockIdx.x, tid = threadIdx.x;
    const float v = g_h[((size_t)(b * Tv + (Tv - 1))) * DMv + tid];

    red[tid] = v; __syncthreads();
    for (int s = 128; s > 0; s >>= 1) { if (tid < s) red[tid] += red[tid + s]; __syncthreads(); }
    const float mu = red[0] * (1.f / DMv);
    __syncthreads();

    const float dv = v - mu;
    red[tid] = dv * dv; __syncthreads();
    for (int s = 128; s > 0; s >>= 1) { if (tid < s) red[tid] += red[tid + s]; __syncthreads(); }
    const float var = red[0] * (1.f / DMv);
    __syncthreads();

    const float hn = dv * rsqrtf(var + 1e-5f) * ln_g[tid] + ln_b[tid];
    red[tid] = hn * head_w[tid]; __syncthreads();
    for (int s = 128; s > 0; s >>= 1) { if (tid < s) red[tid] += red[tid + s]; __syncthreads(); }
    if (tid == 0) out[b] = red[0] + head_b[0];
}

// ---------------------------------------------------------------------------
// Host launcher
// ---------------------------------------------------------------------------
extern "C" void kernel_launch(void* const* d_in, const int* in_sizes, int n_in,
                              void* d_out, int out_size)
{
    const float* x      = (const float*)d_in[0];
    const float* proj_w = (const float*)d_in[1];
    const float* proj_b = (const float*)d_in[2];
    const float* ipw    = (const float*)d_in[3];
    const float* cw     = (const float*)d_in[4];
    const float* cb     = (const float*)d_in[5];
    const float* xpw    = (const float*)d_in[6];
    const float* dtw    = (const float*)d_in[7];
    const float* dtb    = (const float*)d_in[8];
    const float* A_log  = (const float*)d_in[9];
    const float* Dp     = (const float*)d_in[10];
    const float* opw    = (const float*)d_in[11];
    const float* ln_g   = (const float*)d_in[12];
    const float* ln_b   = (const float*)d_in[13];
    const float* head_w = (const float*)d_in[14];
    const float* head_b = (const float*)d_in[15];
    float* out = (float*)d_out;

    float *hbuf, *xzbuf, *ybuf;
    __nv_bfloat16 *whi, *wlo;
    cudaGetSymbolAddress((void**)&hbuf,  g_h);
    cudaGetSymbolAddress((void**)&xzbuf, g_xz);
    cudaGetSymbolAddress((void**)&ybuf,  g_y);
    cudaGetSymbolAddress((void**)&whi,   g_whi);
    cudaGetSymbolAddress((void**)&wlo,   g_wlo);

    __nv_bfloat16* whi_proj = whi;
    __nv_bfloat16* wlo_proj = wlo;
    __nv_bfloat16* whi_ipw  = whi + 16384;
    __nv_bfloat16* wlo_ipw  = wlo + 16384;
    __nv_bfloat16* whi_opw  = whi + 1064960;
    __nv_bfloat16* wlo_opw  = wlo + 1064960;

    // Launches 1-2: weight splits.
    split_ipw_kernel<<<1024, 256>>>(ipw, whi, wlo);
    split_misc_kernel<<<528, 256>>>(proj_w, opw, whi, wlo);

    dim3 grid_in(2, 128);     // N=256/128,  M=8192/64
    dim3 grid_ip(8, 128);     // N=1024/128
    dim3 grid_op(2, 128);     // N=256/128
    dim3 grid_sc(32, 8, 8);   // dgroup x batch x chunk

    // Launch 3: input projection  h = x @ proj_w^T  [8192,256], K=64
    wgemm_nt_kernel<<<grid_in, 256>>>(x, (const float*)0,
                                      whi_proj, wlo_proj, hbuf, BT, DMv, Fv);

    for (int l = 0; l < Lv; ++l) {
        const size_t ipoff = (size_t)l * 262144;
        const size_t opoff = (size_t)l * 131072;
        const float* abias = (l == 0) ? proj_b : (const float*)0;
        const float* alog_l = A_log + (size_t)l * DIv * Nv;

        // Launch 4 (profiled, l==0): in_proj  [8192,1024], K=256
        wgemm_nt_kernel<<<grid_ip, 256>>>(hbuf, abias,
                                          whi_ipw + ipoff, wlo_ipw + ipoff,
                                          xzbuf, BT, 2*DIv, DMv);

        fused_mid_kernel<<<512, 256>>>(
            cw  + (size_t)l * DIv * DCv,
            cb  + (size_t)l * DIv,
            xpw + (size_t)l * (DTRv + 2*Nv) * DIv,
            dtw + (size_t)l * DIv * DTRv,
            dtb + (size_t)l * DIv);

        // chunked scan: pass1 -> prefix -> pass2
        scan_pass1_kernel<<<grid_sc, 256>>>(alog_l);
        scan_prefix_kernel<<<256, 256>>>();
        scan_pass2_kernel<<<grid_sc, 256>>>(alog_l, Dp + (size_t)l * DIv);

        // out_proj: h = y @ opw^T   [8192,256], K=512
        wgemm_nt_kernel<<<grid_op, 256>>>(ybuf, (const float*)0,
                                          whi_opw + opoff, wlo_opw + opoff,
                                          hbuf, BT, DMv, DIv);
    }

    final_kernel<<<Bv, 256>>>(ln_g, ln_b, head_w, head_b, out);
}

// round 10
// speedup vs baseline: 1.3405x; 1.0132x over previous
#include <cuda_runtime.h>
#include <cuda_bf16.h>
#include <mma.h>
#include <math.h>

using namespace nvcuda;

// ---------------------------------------------------------------------------
// Problem constants
// ---------------------------------------------------------------------------
#define Bv   8
#define Tv   1024
#define Fv   64
#define DMv  256
#define Lv   4
#define DIv  512          // 2*DM
#define Nv   16
#define DCv  4
#define DTRv 16           // DM/16
#define BT   (Bv*Tv)      // 8192
#define NCH  8            // scan chunks
#define CHT  128          // timesteps per chunk

// ---------------------------------------------------------------------------
// Scratch (device globals; no runtime allocation allowed)
// ---------------------------------------------------------------------------
__device__ float g_h  [BT * DMv];
__device__ float g_xz [BT * (2*DIv)];
__device__ float g_xc [BT * DIv];
__device__ float g_dt [BT * DIv];
__device__ float g_BC [BT * (2*Nv)];
__device__ float g_y  [BT * DIv];

__device__ float g_chP[Bv * DIv * Nv * NCH];
__device__ float g_chH[Bv * DIv * Nv * NCH];

// split-bf16 weight buffers: proj_w[16384] | ipw[1048576] | opw[524288]
__device__ __nv_bfloat16 g_whi[1589248];
__device__ __nv_bfloat16 g_wlo[1589248];

// ---------------------------------------------------------------------------
// One-shot weight split (proj_w + ipw + opw).
// float4 regions: proj [0,4096), ipw [4096,266240), opw [266240,397312).
// ---------------------------------------------------------------------------
__global__ void __launch_bounds__(256)
split_all_kernel(const float* __restrict__ proj_w,
                 const float* __restrict__ ipw,
                 const float* __restrict__ opw,
                 __nv_bfloat16* __restrict__ whi,
                 __nv_bfloat16* __restrict__ wlo)
{
    const int i = blockIdx.x * 256 + threadIdx.x;
    const float* src;
    int j, dst;
    if (i < 4096)        { src = proj_w; j = i;           dst = 0; }
    else if (i < 266240) { src = ipw;    j = i - 4096;    dst = 16384; }
    else if (i < 397312) { src = opw;    j = i - 266240;  dst = 1064960; }
    else return;

    const float4 v = *(const float4*)(src + j*4);
    __nv_bfloat16* hi = whi + dst + j*4;
    __nv_bfloat16* lo = wlo + dst + j*4;
    __nv_bfloat16 h0 = __float2bfloat16(v.x);
    __nv_bfloat16 h1 = __float2bfloat16(v.y);
    __nv_bfloat16 h2 = __float2bfloat16(v.z);
    __nv_bfloat16 h3 = __float2bfloat16(v.w);
    __nv_bfloat162 a; a.x = h0; a.y = h1;
    __nv_bfloat162 b; b.x = h2; b.y = h3;
    *(__nv_bfloat162*)(hi)     = a;
    *(__nv_bfloat162*)(hi + 2) = b;
    __nv_bfloat162 c; c.x = __float2bfloat16(v.x - __bfloat162float(h0));
                      c.y = __float2bfloat16(v.y - __bfloat162float(h1));
    __nv_bfloat162 d; d.x = __float2bfloat16(v.z - __bfloat162float(h2));
                      d.y = __float2bfloat16(v.w - __bfloat162float(h3));
    *(__nv_bfloat162*)(lo)     = c;
    *(__nv_bfloat162*)(lo + 2) = d;
}

// ---------------------------------------------------------------------------
// Tensor-core GEMM (unchanged from R9).
// ---------------------------------------------------------------------------
#define SPAD 40

__global__ void __launch_bounds__(256, 2)
wgemm_nt_kernel(const float* __restrict__ A, const float* __restrict__ Abias,
                const __nv_bfloat16* __restrict__ Whi,
                const __nv_bfloat16* __restrict__ Wlo,
                float* __restrict__ C,
                int M, int N, int K)
{
    __shared__ __align__(16) __nv_bfloat16 Ah[64*SPAD];
    __shared__ __align__(16) __nv_bfloat16 Al[64*SPAD];
    __shared__ __align__(16) __nv_bfloat16 Bh[128*SPAD];
    __shared__ __align__(16) __nv_bfloat16 Bl[128*SPAD];

    const int tid = threadIdx.x;
    const int bm  = blockIdx.y, bn = blockIdx.x;
    const int wid = tid >> 5;
    const int wm  = wid >> 2;
    const int wn  = wid & 3;

    wmma::fragment<wmma::accumulator, 16, 16, 16, float> acc[2][2];
#pragma unroll
    for (int mi = 0; mi < 2; ++mi)
#pragma unroll
        for (int ni = 0; ni < 2; ++ni)
            wmma::fill_fragment(acc[mi][ni], 0.0f);

    for (int k0 = 0; k0 < K; k0 += 32) {
#pragma unroll
        for (int i = 0; i < 2; ++i) {
            const int idx = tid + i * 256;
            const int row = idx >> 3;
            const int kc  = (idx & 7) << 2;
            float4 v = *(const float4*)(A + (size_t)(bm*64 + row) * K + k0 + kc);
            if (Abias) {
                const float4 bb = *(const float4*)(Abias + k0 + kc);
                v.x += bb.x; v.y += bb.y; v.z += bb.z; v.w += bb.w;
            }
            __nv_bfloat16 h0 = __float2bfloat16(v.x);
            __nv_bfloat16 h1 = __float2bfloat16(v.y);
            __nv_bfloat16 h2 = __float2bfloat16(v.z);
            __nv_bfloat16 h3 = __float2bfloat16(v.w);
            __nv_bfloat162 ph0; ph0.x = h0; ph0.y = h1;
            __nv_bfloat162 ph1; ph1.x = h2; ph1.y = h3;
            *(__nv_bfloat162*)(Ah + row*SPAD + kc)     = ph0;
            *(__nv_bfloat162*)(Ah + row*SPAD + kc + 2) = ph1;
            __nv_bfloat162 pl0; pl0.x = __float2bfloat16(v.x - __bfloat162float(h0));
                                pl0.y = __float2bfloat16(v.y - __bfloat162float(h1));
            __nv_bfloat162 pl1; pl1.x = __float2bfloat16(v.z - __bfloat162float(h2));
                                pl1.y = __float2bfloat16(v.w - __bfloat162float(h3));
            *(__nv_bfloat162*)(Al + row*SPAD + kc)     = pl0;
            *(__nv_bfloat162*)(Al + row*SPAD + kc + 2) = pl1;
        }
#pragma unroll
        for (int i = 0; i < 2; ++i) {
            const int idx = tid + i * 256;
            const int row = idx >> 2;
            const int kc  = (idx & 3) << 3;
            const size_t g = (size_t)(bn*128 + row) * K + k0 + kc;
            *(float4*)(Bh + row*SPAD + kc) = *(const float4*)(Whi + g);
            *(float4*)(Bl + row*SPAD + kc) = *(const float4*)(Wlo + g);
        }
        __syncthreads();

#pragma unroll
        for (int ks = 0; ks < 32; ks += 16) {
            wmma::fragment<wmma::matrix_b, 16, 16, 16, __nv_bfloat16, wmma::col_major> bH[2], bL[2];
#pragma unroll
            for (int ni = 0; ni < 2; ++ni) {
                const int rr = wn*32 + ni*16;
                wmma::load_matrix_sync(bH[ni], Bh + rr*SPAD + ks, SPAD);
                wmma::load_matrix_sync(bL[ni], Bl + rr*SPAD + ks, SPAD);
            }
#pragma unroll
            for (int mi = 0; mi < 2; ++mi) {
                wmma::fragment<wmma::matrix_a, 16, 16, 16, __nv_bfloat16, wmma::row_major> aH, aL;
                const int rr = wm*32 + mi*16;
                wmma::load_matrix_sync(aH, Ah + rr*SPAD + ks, SPAD);
                wmma::load_matrix_sync(aL, Al + rr*SPAD + ks, SPAD);
#pragma unroll
                for (int ni = 0; ni < 2; ++ni) {
                    wmma::mma_sync(acc[mi][ni], aH, bH[ni], acc[mi][ni]);
                    wmma::mma_sync(acc[mi][ni], aH, bL[ni], acc[mi][ni]);
                    wmma::mma_sync(acc[mi][ni], aL, bH[ni], acc[mi][ni]);
                }
            }
        }
        __syncthreads();
    }

#pragma unroll
    for (int mi = 0; mi < 2; ++mi)
#pragma unroll
        for (int ni = 0; ni < 2; ++ni) {
            const int rr = bm*64 + wm*32 + mi*16;
            const int cc = bn*128 + wn*32 + ni*16;
            wmma::store_matrix_sync(C + (size_t)rr * N + cc, acc[mi][ni], N,
                                    wmma::mem_row_major);
        }
}

// ---------------------------------------------------------------------------
// Fused middle kernel v2: float4 smem traffic throughout.
// conv(4)+bias+SiLU -> x_proj -> dt_proj+softplus.  16 t per block.
// ---------------------------------------------------------------------------
__global__ void __launch_bounds__(256)
fused_mid_kernel(const float* __restrict__ conv_w,
                 const float* __restrict__ conv_b,
                 const float* __restrict__ xpw,
                 const float* __restrict__ dtw,
                 const float* __restrict__ dtb)
{
    __shared__ __align__(16) float xc_s  [16][DIv];
    __shared__ __align__(16) float wc_s  [48][68];
    __shared__ __align__(16) float xdbl_s[16][48];

    const int blk = blockIdx.x;
    const int b   = blk >> 6;
    const int t0  = (blk & 63) << 4;
    const int tid = threadIdx.x;

    // ---- conv + SiLU -------------------------------------------------------
#pragma unroll
    for (int dd = 0; dd < 2; ++dd) {
        const int d = tid + dd * 256;
        const float* xin = g_xz + (size_t)(b * Tv) * (2*DIv) + d;
        const float4 cw4 = *(const float4*)(conv_w + d*4);
        const float  cb  = conv_b[d];
        float x0 = (t0 - 3 >= 0) ? xin[(size_t)(t0-3) * (2*DIv)] : 0.f;
        float x1 = (t0 - 2 >= 0) ? xin[(size_t)(t0-2) * (2*DIv)] : 0.f;
        float x2 = (t0 - 1 >= 0) ? xin[(size_t)(t0-1) * (2*DIv)] : 0.f;
#pragma unroll
        for (int tt = 0; tt < 16; ++tt) {
            const float x3 = xin[(size_t)(t0+tt) * (2*DIv)];
            float s = cw4.x*x0 + cw4.y*x1 + cw4.z*x2 + cw4.w*x3 + cb;
            float sl = s / (1.f + __expf(-s));
            xc_s[tt][d] = sl;
            g_xc[((size_t)(b*Tv + t0 + tt)) * DIv + d] = sl;
            x0 = x1; x1 = x2; x2 = x3;
        }
    }
    __syncthreads();

    // ---- x_proj (48 outputs, K=512) with float4 LDS -------------------------
    const int tt  = tid >> 4;
    const int oth = tid & 15;
    float acc0 = 0.f, acc1 = 0.f, acc2 = 0.f;

    for (int kc = 0; kc < DIv; kc += 64) {
#pragma unroll
        for (int j = 0; j < 3; ++j) {
            const int l4 = tid * 3 + j;          // 0..767
            const int o  = l4 >> 4;
            const int k  = (l4 & 15) << 2;
            *(float4*)&wc_s[o][k] = *(const float4*)(xpw + o*DIv + kc + k);
        }
        __syncthreads();
#pragma unroll
        for (int k = 0; k < 64; k += 4) {
            const float4 xa = *(const float4*)&xc_s[tt][kc + k];
            const float4 w0 = *(const float4*)&wc_s[oth      ][k];
            const float4 w1 = *(const float4*)&wc_s[oth + 16][k];
            const float4 w2 = *(const float4*)&wc_s[oth + 32][k];
            acc0 += xa.x*w0.x + xa.y*w0.y + xa.z*w0.z + xa.w*w0.w;
            acc1 += xa.x*w1.x + xa.y*w1.y + xa.z*w1.z + xa.w*w1.w;
            acc2 += xa.x*w2.x + xa.y*w2.y + xa.z*w2.z + xa.w*w2.w;
        }
        __syncthreads();
    }
    xdbl_s[tt][oth     ] = acc0;
    xdbl_s[tt][oth + 16] = acc1;
    xdbl_s[tt][oth + 32] = acc2;
    __syncthreads();

    // ---- write B and C -------------------------------------------------------
    {
        int idx = tid;
#pragma unroll
        for (int r = 0; r < 2; ++r, idx += 256) {
            const int tti = idx >> 5, c = idx & 31;
            g_BC[((size_t)(b*Tv + t0 + tti)) * (2*Nv) + c] = xdbl_s[tti][16 + c];
        }
    }

    // ---- dt_proj + softplus: weights for both channels in regs --------------
    {
        const int d0 = tid, d1 = tid + 256;
        float w0[16], w1[16];
        *(float4*)&w0[0]  = *(const float4*)(dtw + d0*16 + 0);
        *(float4*)&w0[4]  = *(const float4*)(dtw + d0*16 + 4);
        *(float4*)&w0[8]  = *(const float4*)(dtw + d0*16 + 8);
        *(float4*)&w0[12] = *(const float4*)(dtw + d0*16 + 12);
        *(float4*)&w1[0]  = *(const float4*)(dtw + d1*16 + 0);
        *(float4*)&w1[4]  = *(const float4*)(dtw + d1*16 + 4);
        *(float4*)&w1[8]  = *(const float4*)(dtw + d1*16 + 8);
        *(float4*)&w1[12] = *(const float4*)(dtw + d1*16 + 12);
        const float b0 = dtb[d0], b1 = dtb[d1];

#pragma unroll
        for (int tt2 = 0; tt2 < 16; ++tt2) {
            float xv[16];
            *(float4*)&xv[0]  = *(const float4*)&xdbl_s[tt2][0];
            *(float4*)&xv[4]  = *(const float4*)&xdbl_s[tt2][4];
            *(float4*)&xv[8]  = *(const float4*)&xdbl_s[tt2][8];
            *(float4*)&xv[12] = *(const float4*)&xdbl_s[tt2][12];
            float s0 = b0, s1 = b1;
#pragma unroll
            for (int r = 0; r < 16; ++r) {
                s0 += xv[r] * w0[r];
                s1 += xv[r] * w1[r];
            }
            const float sp0 = fmaxf(s0, 0.f) + log1pf(__expf(-fabsf(s0)));
            const float sp1 = fmaxf(s1, 0.f) + log1pf(__expf(-fabsf(s1)));
            const size_t o = ((size_t)(b*Tv + t0 + tt2)) * DIv;
            g_dt[o + d0] = sp0;
            g_dt[o + d1] = sp1;
        }
    }
}

// ---------------------------------------------------------------------------
// Scan pass 1 (unchanged).
// ---------------------------------------------------------------------------
__global__ void __launch_bounds__(256)
scan_pass1_kernel(const float* __restrict__ A_log)
{
    __shared__ float s_dt[64][16];
    __shared__ float s_u [64][16];
    __shared__ float s_b [64][16];

    const int d0   = blockIdx.x * 16;
    const int b    = blockIdx.y;
    const int ch   = blockIdx.z;
    const int tid  = threadIdx.x;
    const int warp = tid >> 5;
    const int lane = tid & 31;
    const int half = lane >> 4;
    const int n    = lane & 15;
    const int dloc = warp * 2 + half;
    const int d    = d0 + dloc;

    const float a = -__expf(A_log[d * Nv + n]);
    float h = 0.f, P = 1.f;

    for (int sc = 0; sc < 2; ++sc) {
        const int base = b * Tv + ch * CHT + sc * 64;
#pragma unroll
        for (int i = 0; i < 4; ++i) {
            const int idx = tid + i * 256;
            const int tt  = idx >> 4;
            const int dd  = idx & 15;
            s_dt[tt][dd] = g_dt[(size_t)(base + tt) * DIv + d0 + dd];
            s_u [tt][dd] = g_xc[(size_t)(base + tt) * DIv + d0 + dd];
            s_b [tt][dd] = g_BC[(size_t)(base + tt) * (2*Nv) + dd];
        }
        __syncthreads();
#pragma unroll 4
        for (int tt = 0; tt < 64; ++tt) {
            const float dtv = s_dt[tt][dloc];
            const float uv  = s_u [tt][dloc];
            const float bv  = s_b [tt][n];
            const float dA  = __expf(dtv * a);
            h = dA * h + (dtv * uv) * bv;
            P *= dA;
        }
        __syncthreads();
    }

    const size_t o = (((size_t)b * DIv + d) * Nv + n) * NCH + ch;
    g_chP[o] = P;
    g_chH[o] = h;
}

// ---------------------------------------------------------------------------
// Prefix over chunks (unchanged).
// ---------------------------------------------------------------------------
__global__ void __launch_bounds__(256)
scan_prefix_kernel()
{
    const int i = blockIdx.x * 256 + threadIdx.x;
    const size_t base = (size_t)i * NCH;
    float4 P0 = *(float4*)(g_chP + base);
    float4 P1 = *(float4*)(g_chP + base + 4);
    float4 H0 = *(float4*)(g_chH + base);
    float4 H1 = *(float4*)(g_chH + base + 4);
    float4 S0, S1;
    float h = 0.f;
    S0.x = h; h = P0.x*h + H0.x;
    S0.y = h; h = P0.y*h + H0.y;
    S0.z = h; h = P0.z*h + H0.z;
    S0.w = h; h = P0.w*h + H0.w;
    S1.x = h; h = P1.x*h + H1.x;
    S1.y = h; h = P1.y*h + H1.y;
    S1.z = h; h = P1.z*h + H1.z;
    S1.w = h;
    *(float4*)(g_chH + base)     = S0;
    *(float4*)(g_chH + base + 4) = S1;
}

// ---------------------------------------------------------------------------
// Scan pass 2 (unchanged).
// ---------------------------------------------------------------------------
__global__ void __launch_bounds__(256)
scan_pass2_kernel(const float* __restrict__ A_log, const float* __restrict__ Dp)
{
    __shared__ float s_dt[64][16];
    __shared__ float s_u [64][16];
    __shared__ float s_z [64][16];
    __shared__ float s_bc[64][32];

    const int d0   = blockIdx.x * 16;
    const int b    = blockIdx.y;
    const int ch   = blockIdx.z;
    const int tid  = threadIdx.x;
    const int warp = tid >> 5;
    const int lane = tid & 31;
    const int half = lane >> 4;
    const int n    = lane & 15;
    const int dloc = warp * 2 + half;
    const int d    = d0 + dloc;

    const float a     = -__expf(A_log[d * Nv + n]);
    const float dcoef = Dp[d];
    float h = g_chH[(((size_t)b * DIv + d) * Nv + n) * NCH + ch];

    for (int sc = 0; sc < 2; ++sc) {
        const int base = b * Tv + ch * CHT + sc * 64;
#pragma unroll
        for (int i = 0; i < 4; ++i) {
            const int idx = tid + i * 256;
            const int tt  = idx >> 4;
            const int dd  = idx & 15;
            s_dt[tt][dd] = g_dt[(size_t)(base + tt) * DIv + d0 + dd];
            s_u [tt][dd] = g_xc[(size_t)(base + tt) * DIv + d0 + dd];
            s_z [tt][dd] = g_xz[(size_t)(base + tt) * (2*DIv) + DIv + d0 + dd];
        }
#pragma unroll
        for (int i = 0; i < 8; ++i) {
            const int idx = tid + i * 256;
            const int tt  = idx >> 5;
            const int c   = idx & 31;
            s_bc[tt][c] = g_BC[(size_t)(base + tt) * (2*Nv) + c];
        }
        __syncthreads();

#pragma unroll 4
        for (int tt = 0; tt < 64; ++tt) {
            const float dtv = s_dt[tt][dloc];
            const float uv  = s_u [tt][dloc];
            const float bv  = s_bc[tt][n];
            const float cv  = s_bc[tt][Nv + n];

            const float dA = __expf(dtv * a);
            h = dA * h + (dtv * uv) * bv;

            float part = h * cv;
            part += __shfl_xor_sync(0xffffffffu, part, 1);
            part += __shfl_xor_sync(0xffffffffu, part, 2);
            part += __shfl_xor_sync(0xffffffffu, part, 4);
            part += __shfl_xor_sync(0xffffffffu, part, 8);

            if (n == 0) {
                const float zv = s_z[tt][dloc];
                float y = part + dcoef * uv;
                y *= zv / (1.f + __expf(-zv));
                g_y[(size_t)(base + tt) * DIv + d] = y;
            }
        }
        __syncthreads();
    }
}

// ---------------------------------------------------------------------------
// Final: LayerNorm(last token) + head.
// ---------------------------------------------------------------------------
__global__ void __launch_bounds__(256)
final_kernel(const float* __restrict__ ln_g, const float* __restrict__ ln_b,
             const float* __restrict__ head_w, const float* __restrict__ head_b,
             float* __restrict__ out)
{
    __shared__ float red[256];
    const int b = blockIdx.x, tid = threadIdx.x;
    const float v = g_h[((size_t)(b * Tv + (Tv - 1))) * DMv + tid];

    red[tid] = v; __syncthreads();
    for (int s = 128; s > 0; s >>= 1) { if (tid < s) red[tid] += red[tid + s]; __syncthreads(); }
    const float mu = red[0] * (1.f / DMv);
    __syncthreads();

    const float dv = v - mu;
    red[tid] = dv * dv; __syncthreads();
    for (int s = 128; s > 0; s >>= 1) { if (tid < s) red[tid] += red[tid + s]; __syncthreads(); }
    const float var = red[0] * (1.f / DMv);
    __syncthreads();

    const float hn = dv * rsqrtf(var + 1e-5f) * ln_g[tid] + ln_b[tid];
    red[tid] = hn * head_w[tid]; __syncthreads();
    for (int s = 128; s > 0; s >>= 1) { if (tid < s) red[tid] += red[tid + s]; __syncthreads(); }
    if (tid == 0) out[b] = red[0] + head_b[0];
}

// ---------------------------------------------------------------------------
// Host launcher
// ---------------------------------------------------------------------------
extern "C" void kernel_launch(void* const* d_in, const int* in_sizes, int n_in,
                              void* d_out, int out_size)
{
    const float* x      = (const float*)d_in[0];
    const float* proj_w = (const float*)d_in[1];
    const float* proj_b = (const float*)d_in[2];
    const float* ipw    = (const float*)d_in[3];
    const float* cw     = (const float*)d_in[4];
    const float* cb     = (const float*)d_in[5];
    const float* xpw    = (const float*)d_in[6];
    const float* dtw    = (const float*)d_in[7];
    const float* dtb    = (const float*)d_in[8];
    const float* A_log  = (const float*)d_in[9];
    const float* Dp     = (const float*)d_in[10];
    const float* opw    = (const float*)d_in[11];
    const float* ln_g   = (const float*)d_in[12];
    const float* ln_b   = (const float*)d_in[13];
    const float* head_w = (const float*)d_in[14];
    const float* head_b = (const float*)d_in[15];
    float* out = (float*)d_out;

    float *hbuf, *xzbuf, *ybuf;
    __nv_bfloat16 *whi, *wlo;
    cudaGetSymbolAddress((void**)&hbuf,  g_h);
    cudaGetSymbolAddress((void**)&xzbuf, g_xz);
    cudaGetSymbolAddress((void**)&ybuf,  g_y);
    cudaGetSymbolAddress((void**)&whi,   g_whi);
    cudaGetSymbolAddress((void**)&wlo,   g_wlo);

    __nv_bfloat16* whi_proj = whi;
    __nv_bfloat16* wlo_proj = wlo;
    __nv_bfloat16* whi_ipw  = whi + 16384;
    __nv_bfloat16* wlo_ipw  = wlo + 16384;
    __nv_bfloat16* whi_opw  = whi + 1064960;
    __nv_bfloat16* wlo_opw  = wlo + 1064960;

    // Launch 1: all weight splits.
    split_all_kernel<<<1552, 256>>>(proj_w, ipw, opw, whi, wlo);

    dim3 grid_in(2, 128);
    dim3 grid_ip(8, 128);
    dim3 grid_op(2, 128);
    dim3 grid_sc(32, 8, 8);

    // Launch 2: input projection  h = x @ proj_w^T  [8192,256], K=64
    wgemm_nt_kernel<<<grid_in, 256>>>(x, (const float*)0,
                                      whi_proj, wlo_proj, hbuf, BT, DMv, Fv);

    for (int l = 0; l < Lv; ++l) {
        const size_t ipoff = (size_t)l * 262144;
        const size_t opoff = (size_t)l * 131072;
        const float* abias = (l == 0) ? proj_b : (const float*)0;
        const float* alog_l = A_log + (size_t)l * DIv * Nv;

        // Launch 3: in_proj  [8192,1024], K=256
        wgemm_nt_kernel<<<grid_ip, 256>>>(hbuf, abias,
                                          whi_ipw + ipoff, wlo_ipw + ipoff,
                                          xzbuf, BT, 2*DIv, DMv);

        // Launch 4 (profiled, l==0): fused_mid v2
        fused_mid_kernel<<<512, 256>>>(
            cw  + (size_t)l * DIv * DCv,
            cb  + (size_t)l * DIv,
            xpw + (size_t)l * (DTRv + 2*Nv) * DIv,
            dtw + (size_t)l * DIv * DTRv,
            dtb + (size_t)l * DIv);

        scan_pass1_kernel<<<grid_sc, 256>>>(alog_l);
        scan_prefix_kernel<<<256, 256>>>();
        scan_pass2_kernel<<<grid_sc, 256>>>(alog_l, Dp + (size_t)l * DIv);

        // out_proj: h = y @ opw^T   [8192,256], K=512
        wgemm_nt_kernel<<<grid_op, 256>>>(ybuf, (const float*)0,
                                          whi_opw + opoff, wlo_opw + opoff,
                                          hbuf, BT, DMv, DIv);
    }

    final_kernel<<<Bv, 256>>>(ln_g, ln_b, head_w, head_b, out);
}